// round 2
// baseline (speedup 1.0000x reference)
#include <cuda_runtime.h>
#include <cstdint>

#define H 512
#define DB 128
#define DC 16
#define NB 2048   // batch N

// ---------------- scratch (no allocations allowed) ----------------
__device__ float g_x1[NB * 2 * H];      // 2048 x 1024
__device__ float g_x2[NB * 3 * H];      // 2048 x 1536
__device__ float g_x3[NB * 3 * H];      // 2048 x 1536
__device__ float g_x4[NB * 2 * H];      // 2048 x 1024
__device__ float g_Ms[NB * DB * DC];    // 2048 x 2048
__device__ float g_outT[NB * DB];       // 2048 x 128

// ---------------- tiled fp32 GEMM: C = act(A @ B + bias) ----------------
// A: [M,K] row-major, B: [K,N] row-major, C: [M,N]
#define BM 128
#define BN 128
#define BKK 16
#define TM 8
#define TN 8

__global__ __launch_bounds__(256, 2) void sgemm_kernel(
    const float* __restrict__ A, const float* __restrict__ B,
    const float* __restrict__ bias, float* __restrict__ C,
    int M, int N, int K, int do_relu)
{
    __shared__ float As[BKK][BM];   // transposed A tile
    __shared__ float Bs[BKK][BN];

    const int tid = threadIdx.x;
    const int m0 = blockIdx.y * BM;
    const int n0 = blockIdx.x * BN;
    const int tx = tid & 15;        // 0..15 -> n
    const int ty = tid >> 4;        // 0..15 -> m

    float acc[TM][TN];
#pragma unroll
    for (int u = 0; u < TM; u++)
#pragma unroll
        for (int v = 0; v < TN; v++) acc[u][v] = 0.0f;

    for (int k0 = 0; k0 < K; k0 += BKK) {
        // Load A tile: 128 rows x 16 cols = 512 float4
#pragma unroll
        for (int t = 0; t < 2; t++) {
            int i = tid + t * 256;          // 0..511
            int row = i >> 2;
            int kq = i & 3;
            float4 v = *(const float4*)&A[(size_t)(m0 + row) * K + k0 + kq * 4];
            As[kq * 4 + 0][row] = v.x;
            As[kq * 4 + 1][row] = v.y;
            As[kq * 4 + 2][row] = v.z;
            As[kq * 4 + 3][row] = v.w;
        }
        // Load B tile: 16 rows x 128 cols = 512 float4
#pragma unroll
        for (int t = 0; t < 2; t++) {
            int i = tid + t * 256;
            int row = i >> 5;               // 0..15
            int nq = i & 31;
            *(float4*)&Bs[row][nq * 4] =
                *(const float4*)&B[(size_t)(k0 + row) * N + n0 + nq * 4];
        }
        __syncthreads();

#pragma unroll
        for (int k = 0; k < BKK; k++) {
            float a[TM], b[TN];
#pragma unroll
            for (int u = 0; u < TM; u++) a[u] = As[k][ty * TM + u];
#pragma unroll
            for (int v = 0; v < TN; v++) b[v] = Bs[k][tx * TN + v];
#pragma unroll
            for (int u = 0; u < TM; u++)
#pragma unroll
                for (int v = 0; v < TN; v++)
                    acc[u][v] = fmaf(a[u], b[v], acc[u][v]);
        }
        __syncthreads();
    }

    // epilogue: bias + relu, vectorized stores
    float bfrag[TN];
#pragma unroll
    for (int v = 0; v < TN; v++)
        bfrag[v] = bias ? bias[n0 + tx * TN + v] : 0.0f;

#pragma unroll
    for (int u = 0; u < TM; u++) {
        int row = m0 + ty * TM + u;
        float x[TN];
#pragma unroll
        for (int v = 0; v < TN; v++) {
            float t = acc[u][v] + bfrag[v];
            x[v] = do_relu ? fmaxf(t, 0.0f) : t;
        }
        float4* dst = (float4*)&C[(size_t)row * N + n0 + tx * TN];
        dst[0] = make_float4(x[0], x[1], x[2], x[3]);
        dst[1] = make_float4(x[4], x[5], x[6], x[7]);
    }
}

// ---------------- packed f32x2 helpers (sm_103a FFMA2 path) ----------------
__device__ __forceinline__ unsigned long long fma2_u64(
    unsigned long long a, unsigned long long b, unsigned long long c)
{
    unsigned long long r;
    asm("fma.rn.f32x2 %0, %1, %2, %3;" : "=l"(r) : "l"(a), "l"(b), "l"(c));
    return r;
}
__device__ __forceinline__ unsigned long long add2_u64(
    unsigned long long a, unsigned long long b)
{
    unsigned long long r;
    asm("add.rn.f32x2 %0, %1, %2;" : "=l"(r) : "l"(a), "l"(b));
    return r;
}

// ---------------- minibatch discrimination ----------------
// Ms: [N, DB*DC] row-major. outT[i, b] = sum_j exp(-sum_c |Ms[i,b*16+c]-Ms[j,b*16+c]|)
// grid: (N/256, DB), block 256. Each thread owns one row i for one b.
__global__ __launch_bounds__(256) void pairwise_kernel(
    const float* __restrict__ Ms, float* __restrict__ outT)
{
    const int ROWW = DB * DC;   // 2048
    const int b = blockIdx.y;
    const int i = blockIdx.x * 256 + threadIdx.x;

    const unsigned long long NEG1x2 = 0xBF800000BF800000ull;
    const unsigned long long ABSM   = 0x7FFFFFFF7FFFFFFFull;

    unsigned long long mi[DC / 2];
#pragma unroll
    for (int p = 0; p < DC / 2; p++)
        mi[p] = *(const unsigned long long*)&Ms[(size_t)i * ROWW + b * DC + p * 2];

    __shared__ float sj[128][DC];   // 8 KB j-tile
    float acc = 0.0f;

    for (int jt = 0; jt < NB; jt += 128) {
        // cooperative load: 128 rows x 16 floats = 512 float4
#pragma unroll
        for (int t = 0; t < 2; t++) {
            int idx = threadIdx.x + t * 256;  // 0..511
            int r = idx >> 2;
            int q = idx & 3;
            *(float4*)&sj[r][q * 4] =
                *(const float4*)&Ms[(size_t)(jt + r) * ROWW + b * DC + q * 4];
        }
        __syncthreads();

#pragma unroll 4
        for (int j = 0; j < 128; j++) {
            const unsigned long long* mj = (const unsigned long long*)sj[j];
            unsigned long long a2 = 0ull;   // packed (0.0f, 0.0f)
#pragma unroll
            for (int p = 0; p < DC / 2; p++) {
                unsigned long long t = fma2_u64(mj[p], NEG1x2, mi[p]); // mi - mj
                t &= ABSM;                                            // |.| both halves
                a2 = add2_u64(a2, t);
            }
            float lo = __uint_as_float((unsigned)(a2 & 0xffffffffu));
            float hi = __uint_as_float((unsigned)(a2 >> 32));
            acc += __expf(-(lo + hi));
        }
        __syncthreads();
    }

    outT[(size_t)i * DB + b] = acc;
}

// ---------------- final logits: sigmoid(concat(feature,outT) @ Wo + bo) ----------------
__global__ __launch_bounds__(256) void final_kernel(
    const float* __restrict__ feature, const float* __restrict__ outT,
    const float* __restrict__ Wo, const float* __restrict__ bo,
    float* __restrict__ out)
{
    const int warp = threadIdx.x >> 5;
    const int lane = threadIdx.x & 31;
    const int row = blockIdx.x * 8 + warp;
    if (row >= NB) return;

    float s = 0.0f;
#pragma unroll
    for (int h = lane; h < H; h += 32)
        s = fmaf(feature[(size_t)row * H + h], Wo[h], s);
#pragma unroll
    for (int c = lane; c < DB; c += 32)
        s = fmaf(outT[(size_t)row * DB + c], Wo[H + c], s);

#pragma unroll
    for (int o = 16; o > 0; o >>= 1)
        s += __shfl_xor_sync(0xffffffffu, s, o);

    if (lane == 0) {
        float v = s + bo[0];
        out[row] = 1.0f / (1.0f + __expf(-v));
    }
}

// ---------------- launch ----------------
extern "C" void kernel_launch(void* const* d_in, const int* in_sizes, int n_in,
                              void* d_out, int out_size)
{
    const float* input = (const float*)d_in[0];
    const float* W1 = (const float*)d_in[1];
    const float* b1 = (const float*)d_in[2];
    const float* W2 = (const float*)d_in[3];
    const float* b2 = (const float*)d_in[4];
    const float* Wh = (const float*)d_in[5];
    const float* bh = (const float*)d_in[6];
    const float* W3 = (const float*)d_in[7];
    const float* b3 = (const float*)d_in[8];
    const float* W4 = (const float*)d_in[9];
    const float* b4 = (const float*)d_in[10];
    const float* Wo = (const float*)d_in[11];
    const float* bo = (const float*)d_in[12];
    const float* T  = (const float*)d_in[13];

    float* out = (float*)d_out;
    float* feature = out;              // first NB*H floats of output
    float* logits = out + (size_t)NB * H;

    float *x1, *x2, *x3, *x4, *Ms, *oT;
    cudaGetSymbolAddress((void**)&x1, g_x1);
    cudaGetSymbolAddress((void**)&x2, g_x2);
    cudaGetSymbolAddress((void**)&x3, g_x3);
    cudaGetSymbolAddress((void**)&x4, g_x4);
    cudaGetSymbolAddress((void**)&Ms, g_Ms);
    cudaGetSymbolAddress((void**)&oT, g_outT);

    dim3 blk(256);

    // x1 = relu(input @ W1 + b1)   [2048,1024]
    sgemm_kernel<<<dim3(1024 / BN, NB / BM), blk>>>(input, W1, b1, x1, NB, 1024, 512, 1);
    // x2 = relu(x1 @ W2 + b2)      [2048,1536]
    sgemm_kernel<<<dim3(1536 / BN, NB / BM), blk>>>(x1, W2, b2, x2, NB, 1536, 1024, 1);
    // x3 = relu(x2 @ Wh + bh)      [2048,1536]
    sgemm_kernel<<<dim3(1536 / BN, NB / BM), blk>>>(x2, Wh, bh, x3, NB, 1536, 1536, 1);
    // x4 = relu(x3 @ W3 + b3)      [2048,1024]
    sgemm_kernel<<<dim3(1024 / BN, NB / BM), blk>>>(x3, W3, b3, x4, NB, 1024, 1536, 1);
    // feature = relu(x4 @ W4 + b4) [2048,512] -> directly into d_out
    sgemm_kernel<<<dim3(512 / BN, NB / BM), blk>>>(x4, W4, b4, feature, NB, 512, 1024, 1);
    // Ms = feature @ T             [2048,2048], no bias, no relu
    sgemm_kernel<<<dim3(2048 / BN, NB / BM), blk>>>(feature, T, nullptr, Ms, NB, 2048, 512, 0);

    // minibatch discrimination
    pairwise_kernel<<<dim3(NB / 256, DB), blk>>>(Ms, oT);

    // logits + sigmoid
    final_kernel<<<NB / 8, blk>>>(feature, oT, Wo, bo, logits);
}

// round 5
// speedup vs baseline: 1.3265x; 1.3265x over previous
#include <cuda_runtime.h>
#include <cuda_bf16.h>
#include <cstdint>

typedef unsigned short u16;

#define H 512
#define DB 128
#define DC 16
#define NB 2048

// ---------------- scratch panels (bf16 x3 split, K' = 3K concatenation) ----------------
// A' panels: [M, 3K] row-major = [Ah | Al | Ah]
__device__ __align__(16) u16 g_A0[2048 * 1536];
__device__ __align__(16) u16 g_A1[2048 * 3072];
__device__ __align__(16) u16 g_A2[2048 * 4608];
__device__ __align__(16) u16 g_A3[2048 * 4608];
__device__ __align__(16) u16 g_A4[2048 * 3072];
__device__ __align__(16) u16 g_A5[2048 * 1536];
// B' panels: [N, 3K] row-major (k contiguous) = [Bh | Bh | Bl]
__device__ __align__(16) u16 g_B1[1024 * 1536];
__device__ __align__(16) u16 g_B2[1536 * 3072];
__device__ __align__(16) u16 g_BH[1536 * 4608];
__device__ __align__(16) u16 g_B3[1024 * 4608];
__device__ __align__(16) u16 g_B4[512  * 3072];
__device__ __align__(16) u16 g_B6[2048 * 1536];
__device__ float g_Ms[NB * DB * DC];
__device__ float g_outT[NB * DB];

// ---------------- helpers ----------------
__device__ __forceinline__ uint32_t smem_u32(const void* p) {
    uint32_t a;
    asm("{ .reg .u64 t; cvta.to.shared.u64 t, %1; cvt.u32.u64 %0, t; }" : "=r"(a) : "l"(p));
    return a;
}
__device__ __forceinline__ void cp16(uint32_t s, const void* g) {
    asm volatile("cp.async.cg.shared.global [%0], [%1], 16;" :: "r"(s), "l"(g) : "memory");
}
__device__ __forceinline__ void cp_commit() { asm volatile("cp.async.commit_group;" ::: "memory"); }
__device__ __forceinline__ void cp_wait1()  { asm volatile("cp.async.wait_group 1;" ::: "memory"); }
__device__ __forceinline__ void cp_wait0()  { asm volatile("cp.async.wait_group 0;" ::: "memory"); }

__device__ __forceinline__ void mma_bf16(float* d,
    uint32_t a0, uint32_t a1, uint32_t a2, uint32_t a3, uint32_t b0, uint32_t b1)
{
    asm volatile("mma.sync.aligned.m16n8k16.row.col.f32.bf16.bf16.f32 "
        "{%0,%1,%2,%3}, {%4,%5,%6,%7}, {%8,%9}, {%0,%1,%2,%3};"
        : "+f"(d[0]), "+f"(d[1]), "+f"(d[2]), "+f"(d[3])
        : "r"(a0), "r"(a1), "r"(a2), "r"(a3), "r"(b0), "r"(b1));
}

__device__ __forceinline__ void split8(const float* x, uint4& hv, uint4& lv) {
    unsigned hs[8], ls[8];
#pragma unroll
    for (int i = 0; i < 8; i++) {
        __nv_bfloat16 h = __float2bfloat16(x[i]);
        float hf = __bfloat162float(h);
        __nv_bfloat16 l = __float2bfloat16(x[i] - hf);
        hs[i] = (unsigned)__bfloat16_as_ushort(h);
        ls[i] = (unsigned)__bfloat16_as_ushort(l);
    }
    hv.x = hs[0] | (hs[1] << 16); hv.y = hs[2] | (hs[3] << 16);
    hv.z = hs[4] | (hs[5] << 16); hv.w = hs[6] | (hs[7] << 16);
    lv.x = ls[0] | (ls[1] << 16); lv.y = ls[2] | (ls[3] << 16);
    lv.z = ls[4] | (ls[5] << 16); lv.w = ls[6] | (ls[7] << 16);
}

// ---------------- convert A: fp32 [NB,K] -> A' bf16 [NB, 3K] = [Ah|Al|Ah] ----------------
__global__ __launch_bounds__(256) void convert_A(
    const float* __restrict__ A, u16* __restrict__ P, int K)
{
    int CPR = K >> 3;
    int id = blockIdx.x * 256 + threadIdx.x;
    if (id >= NB * CPR) return;
    int r = id / CPR, c8 = id - r * CPR;
    float x[8];
    *(float4*)&x[0] = *(const float4*)&A[(size_t)r * K + c8 * 8];
    *(float4*)&x[4] = *(const float4*)&A[(size_t)r * K + c8 * 8 + 4];
    uint4 hv, lv;
    split8(x, hv, lv);
    int K3 = 3 * K;
    size_t base = (size_t)r * K3 + c8 * 8;
    *(uint4*)&P[base]         = hv;
    *(uint4*)&P[base + K]     = lv;
    *(uint4*)&P[base + 2 * K] = hv;
}

// ---------------- convert B: W fp32 [K,N] -> B' bf16 [N, 3K] = [Bh|Bh|Bl] ----------------
__global__ __launch_bounds__(256) void convert_B(
    const float* __restrict__ W, u16* __restrict__ P, int K, int N)
{
    __shared__ float ts[64][68];
    int n0 = blockIdx.x * 64, k0 = blockIdx.y * 64;
#pragma unroll
    for (int t = 0; t < 4; t++) {
        int i = threadIdx.x + t * 256;     // 0..1023
        int row = i >> 4, q = i & 15;
        *(float4*)&ts[row][q * 4] = *(const float4*)&W[(size_t)(k0 + row) * N + n0 + q * 4];
    }
    __syncthreads();
    int K3 = 3 * K;
#pragma unroll
    for (int t = 0; t < 2; t++) {
        int s = threadIdx.x + t * 256;     // 0..511
        int n = s >> 3, c8 = s & 7;
        float x[8];
#pragma unroll
        for (int i = 0; i < 8; i++) x[i] = ts[c8 * 8 + i][n];
        uint4 hv, lv;
        split8(x, hv, lv);
        size_t base = (size_t)(n0 + n) * K3 + k0 + c8 * 8;
        // FIX (R4 bug): segment order must be [Bh | Bh | Bl] to pair with A' = [Ah | Al | Ah]
        *(uint4*)&P[base]         = hv;
        *(uint4*)&P[base + K]     = hv;
        *(uint4*)&P[base + 2 * K] = lv;
    }
}

// ---------------- bf16 mma.sync GEMM: CTA 128x128, warp 32x64, BK=32, double-buffered ----------------
#define PADK 40   // bf16 row stride in SMEM

__global__ __launch_bounds__(256, 2) void gemm_mma(
    const u16* __restrict__ A, const u16* __restrict__ B,
    const float* __restrict__ bias, int K3, int relu,
    float* __restrict__ outF, int ldF, u16* __restrict__ outP)
{
    __shared__ u16 As[2][128 * PADK];
    __shared__ u16 Bs[2][128 * PADK];
    __shared__ float bias_s[128];

    const int tid = threadIdx.x;
    const int m0 = blockIdx.y * 128, n0 = blockIdx.x * 128;
    const int Nfull = gridDim.x * 128;
    const int lane = tid & 31, wid = tid >> 5;
    const int g = lane >> 2, tig = lane & 3;
    const int wm = (wid & 3) * 32, wn = (wid >> 2) * 64;

    if (tid < 128) bias_s[tid] = bias ? bias[n0 + tid] : 0.0f;

    const u16* Ag = A + (size_t)m0 * K3;
    const u16* Bg = B + (size_t)n0 * K3;

    float acc[2][8][4];
#pragma unroll
    for (int mf = 0; mf < 2; mf++)
#pragma unroll
        for (int nf = 0; nf < 8; nf++)
#pragma unroll
            for (int q = 0; q < 4; q++) acc[mf][nf][q] = 0.0f;

    const int nchunk = K3 >> 5;
    const int lr = (tid >> 2);          // 0..63
    const int lc = (tid & 3) * 8;       // bf16 col offset of 16B chunk

    // prefetch chunk 0
    {
#pragma unroll
        for (int p = 0; p < 2; p++) {
            int r = lr + p * 64;
            cp16(smem_u32(&As[0][r * PADK + lc]), Ag + (size_t)r * K3 + lc);
            cp16(smem_u32(&Bs[0][r * PADK + lc]), Bg + (size_t)r * K3 + lc);
        }
        cp_commit();
    }

    for (int kc = 0; kc < nchunk; kc++) {
        if (kc + 1 < nchunk) {
            int k0 = (kc + 1) << 5;
            int buf = (kc + 1) & 1;
#pragma unroll
            for (int p = 0; p < 2; p++) {
                int r = lr + p * 64;
                cp16(smem_u32(&As[buf][r * PADK + lc]), Ag + (size_t)r * K3 + k0 + lc);
                cp16(smem_u32(&Bs[buf][r * PADK + lc]), Bg + (size_t)r * K3 + k0 + lc);
            }
            cp_commit();
            cp_wait1();
        } else {
            cp_wait0();
        }
        __syncthreads();

        const int buf = kc & 1;
#pragma unroll
        for (int ks = 0; ks < 2; ks++) {
            const int kk = (ks << 4) + tig * 2;
            uint32_t bfr[8][2];
#pragma unroll
            for (int nf = 0; nf < 8; nf++) {
                int rn = wn + nf * 8 + g;
                bfr[nf][0] = *(const uint32_t*)&Bs[buf][rn * PADK + kk];
                bfr[nf][1] = *(const uint32_t*)&Bs[buf][rn * PADK + kk + 8];
            }
#pragma unroll
            for (int mf = 0; mf < 2; mf++) {
                int rm = wm + mf * 16 + g;
                uint32_t a0 = *(const uint32_t*)&As[buf][rm * PADK + kk];
                uint32_t a1 = *(const uint32_t*)&As[buf][(rm + 8) * PADK + kk];
                uint32_t a2 = *(const uint32_t*)&As[buf][rm * PADK + kk + 8];
                uint32_t a3 = *(const uint32_t*)&As[buf][(rm + 8) * PADK + kk + 8];
#pragma unroll
                for (int nf = 0; nf < 8; nf++)
                    mma_bf16(acc[mf][nf], a0, a1, a2, a3, bfr[nf][0], bfr[nf][1]);
            }
        }
        __syncthreads();
    }

    // epilogue: bias + relu; optional fp32 out; optional next-layer A' panel [M, 3N] = [Ah|Al|Ah]
    const int K3n = 3 * Nfull;
#pragma unroll
    for (int mf = 0; mf < 2; mf++) {
#pragma unroll
        for (int hrow = 0; hrow < 2; hrow++) {
            int row = m0 + wm + mf * 16 + g + hrow * 8;
#pragma unroll
            for (int nf = 0; nf < 8; nf++) {
                int cl = wn + nf * 8 + tig * 2;
                float v0 = acc[mf][nf][hrow * 2 + 0] + bias_s[cl];
                float v1 = acc[mf][nf][hrow * 2 + 1] + bias_s[cl + 1];
                if (relu) { v0 = fmaxf(v0, 0.0f); v1 = fmaxf(v1, 0.0f); }
                int col = n0 + cl;
                if (outF)
                    *(float2*)&outF[(size_t)row * ldF + col] = make_float2(v0, v1);
                if (outP) {
                    __nv_bfloat16 h0 = __float2bfloat16(v0), h1 = __float2bfloat16(v1);
                    float l0 = v0 - __bfloat162float(h0);
                    float l1 = v1 - __bfloat162float(h1);
                    __nv_bfloat16 g0 = __float2bfloat16(l0), g1 = __float2bfloat16(l1);
                    uint32_t hp = (uint32_t)__bfloat16_as_ushort(h0) |
                                  ((uint32_t)__bfloat16_as_ushort(h1) << 16);
                    uint32_t lp = (uint32_t)__bfloat16_as_ushort(g0) |
                                  ((uint32_t)__bfloat16_as_ushort(g1) << 16);
                    size_t base = (size_t)row * K3n + col;
                    *(uint32_t*)&outP[base]             = hp;
                    *(uint32_t*)&outP[base + Nfull]     = lp;
                    *(uint32_t*)&outP[base + 2 * Nfull] = hp;
                }
            }
        }
    }
}

// ---------------- packed f32x2 helpers ----------------
__device__ __forceinline__ unsigned long long fma2_u64(
    unsigned long long a, unsigned long long b, unsigned long long c)
{
    unsigned long long r;
    asm("fma.rn.f32x2 %0, %1, %2, %3;" : "=l"(r) : "l"(a), "l"(b), "l"(c));
    return r;
}
__device__ __forceinline__ unsigned long long add2_u64(unsigned long long a, unsigned long long b)
{
    unsigned long long r;
    asm("add.rn.f32x2 %0, %1, %2;" : "=l"(r) : "l"(a), "l"(b));
    return r;
}

// ---------------- minibatch discrimination ----------------
__global__ __launch_bounds__(256) void pairwise_kernel(
    const float* __restrict__ Ms, float* __restrict__ outT)
{
    const int ROWW = DB * DC;
    const int b = blockIdx.y;
    const int i = blockIdx.x * 256 + threadIdx.x;

    const unsigned long long NEG1x2 = 0xBF800000BF800000ull;
    const unsigned long long ABSM   = 0x7FFFFFFF7FFFFFFFull;

    unsigned long long mi[DC / 2];
#pragma unroll
    for (int p = 0; p < DC / 2; p++)
        mi[p] = *(const unsigned long long*)&Ms[(size_t)i * ROWW + b * DC + p * 2];

    __shared__ float sj[128][DC];
    float acc = 0.0f;

    for (int jt = 0; jt < NB; jt += 128) {
#pragma unroll
        for (int t = 0; t < 2; t++) {
            int idx = threadIdx.x + t * 256;
            int r = idx >> 2;
            int q = idx & 3;
            *(float4*)&sj[r][q * 4] =
                *(const float4*)&Ms[(size_t)(jt + r) * ROWW + b * DC + q * 4];
        }
        __syncthreads();

#pragma unroll 4
        for (int j = 0; j < 128; j++) {
            const unsigned long long* mj = (const unsigned long long*)sj[j];
            unsigned long long a2 = 0ull;
#pragma unroll
            for (int p = 0; p < DC / 2; p++) {
                unsigned long long t = fma2_u64(mj[p], NEG1x2, mi[p]);
                t &= ABSM;
                a2 = add2_u64(a2, t);
            }
            float lo = __uint_as_float((unsigned)(a2 & 0xffffffffu));
            float hi = __uint_as_float((unsigned)(a2 >> 32));
            acc += __expf(-(lo + hi));
        }
        __syncthreads();
    }
    outT[(size_t)i * DB + b] = acc;
}

// ---------------- final logits ----------------
__global__ __launch_bounds__(256) void final_kernel(
    const float* __restrict__ feature, const float* __restrict__ outT,
    const float* __restrict__ Wo, const float* __restrict__ bo,
    float* __restrict__ out)
{
    const int warp = threadIdx.x >> 5;
    const int lane = threadIdx.x & 31;
    const int row = blockIdx.x * 8 + warp;
    if (row >= NB) return;

    float s = 0.0f;
#pragma unroll
    for (int h = lane; h < H; h += 32)
        s = fmaf(feature[(size_t)row * H + h], Wo[h], s);
#pragma unroll
    for (int c = lane; c < DB; c += 32)
        s = fmaf(outT[(size_t)row * DB + c], Wo[H + c], s);
#pragma unroll
    for (int o = 16; o > 0; o >>= 1)
        s += __shfl_xor_sync(0xffffffffu, s, o);
    if (lane == 0) {
        float v = s + bo[0];
        out[row] = 1.0f / (1.0f + __expf(-v));
    }
}

// ---------------- launch ----------------
extern "C" void kernel_launch(void* const* d_in, const int* in_sizes, int n_in,
                              void* d_out, int out_size)
{
    const float* input = (const float*)d_in[0];
    const float* W1 = (const float*)d_in[1];
    const float* b1 = (const float*)d_in[2];
    const float* W2 = (const float*)d_in[3];
    const float* b2 = (const float*)d_in[4];
    const float* Wh = (const float*)d_in[5];
    const float* bh = (const float*)d_in[6];
    const float* W3 = (const float*)d_in[7];
    const float* b3 = (const float*)d_in[8];
    const float* W4 = (const float*)d_in[9];
    const float* b4 = (const float*)d_in[10];
    const float* Wo = (const float*)d_in[11];
    const float* bo = (const float*)d_in[12];
    const float* T  = (const float*)d_in[13];

    float* out = (float*)d_out;
    float* feature = out;
    float* logits = out + (size_t)NB * H;

    u16 *A0, *A1, *A2, *A3, *A4, *A5, *B1, *B2, *BHp, *B3p, *B4p, *B6;
    float *Ms, *oT;
    cudaGetSymbolAddress((void**)&A0, g_A0);
    cudaGetSymbolAddress((void**)&A1, g_A1);
    cudaGetSymbolAddress((void**)&A2, g_A2);
    cudaGetSymbolAddress((void**)&A3, g_A3);
    cudaGetSymbolAddress((void**)&A4, g_A4);
    cudaGetSymbolAddress((void**)&A5, g_A5);
    cudaGetSymbolAddress((void**)&B1, g_B1);
    cudaGetSymbolAddress((void**)&B2, g_B2);
    cudaGetSymbolAddress((void**)&BHp, g_BH);
    cudaGetSymbolAddress((void**)&B3p, g_B3);
    cudaGetSymbolAddress((void**)&B4p, g_B4);
    cudaGetSymbolAddress((void**)&B6, g_B6);
    cudaGetSymbolAddress((void**)&Ms, g_Ms);
    cudaGetSymbolAddress((void**)&oT, g_outT);

    // conversions to bf16x3 panels
    convert_A<<<(NB * (512 / 8) + 255) / 256, 256>>>(input, A0, 512);
    convert_B<<<dim3(1024 / 64, 512 / 64),  256>>>(W1, B1, 512, 1024);
    convert_B<<<dim3(1536 / 64, 1024 / 64), 256>>>(W2, B2, 1024, 1536);
    convert_B<<<dim3(1536 / 64, 1536 / 64), 256>>>(Wh, BHp, 1536, 1536);
    convert_B<<<dim3(1024 / 64, 1536 / 64), 256>>>(W3, B3p, 1536, 1024);
    convert_B<<<dim3(512 / 64, 1024 / 64),  256>>>(W4, B4p, 1024, 512);
    convert_B<<<dim3(2048 / 64, 512 / 64),  256>>>(T, B6, 512, 2048);

    // GEMM chain on mma.sync bf16 (K' = 3K), epilogues emit next-layer panels
    gemm_mma<<<dim3(8, 16),  256>>>(A0, B1,  b1, 1536, 1, nullptr, 0,    A1);
    gemm_mma<<<dim3(12, 16), 256>>>(A1, B2,  b2, 3072, 1, nullptr, 0,    A2);
    gemm_mma<<<dim3(12, 16), 256>>>(A2, BHp, bh, 4608, 1, nullptr, 0,    A3);
    gemm_mma<<<dim3(8, 16),  256>>>(A3, B3p, b3, 4608, 1, nullptr, 0,    A4);
    gemm_mma<<<dim3(4, 16),  256>>>(A4, B4p, b4, 3072, 1, feature, 512,  A5);
    gemm_mma<<<dim3(16, 16), 256>>>(A5, B6,  nullptr, 1536, 0, Ms, 2048, nullptr);

    // minibatch discrimination + logits
    pairwise_kernel<<<dim3(NB / 256, DB), 256>>>(Ms, oT);
    final_kernel<<<NB / 8, 256>>>(feature, oT, Wo, bo, logits);
}

// round 8
// speedup vs baseline: 1.5829x; 1.1933x over previous
#include <cuda_runtime.h>
#include <cuda_bf16.h>
#include <cstdint>

typedef unsigned short u16;
typedef unsigned long long u64;

#define H 512
#define DB 128
#define DC 16
#define NB 2048

// ---------------- scratch panels (bf16 x3 split, K' = 3K concatenation) ----------------
// A' panels: [M, 3K] row-major = [Ah | Al | Ah]
__device__ __align__(16) u16 g_A0[2048 * 1536];
__device__ __align__(16) u16 g_A1[2048 * 3072];
__device__ __align__(16) u16 g_A2[2048 * 4608];
__device__ __align__(16) u16 g_A3[2048 * 4608];
__device__ __align__(16) u16 g_A4[2048 * 3072];
__device__ __align__(16) u16 g_A5[2048 * 1536];
// B' panels: [N, 3K] row-major (k contiguous) = [Bh | Bh | Bl]
__device__ __align__(16) u16 g_B1[1024 * 1536];
__device__ __align__(16) u16 g_B2[1536 * 3072];
__device__ __align__(16) u16 g_BH[1536 * 4608];
__device__ __align__(16) u16 g_B3[1024 * 4608];
__device__ __align__(16) u16 g_B4[512  * 3072];
__device__ __align__(16) u16 g_B6[2048 * 1536];
__device__ __align__(16) float g_Ms[NB * DB * DC];
__device__ __align__(16) float g_outT[NB * DB];

// ---------------- helpers ----------------
__device__ __forceinline__ uint32_t smem_u32(const void* p) {
    uint32_t a;
    asm("{ .reg .u64 t; cvta.to.shared.u64 t, %1; cvt.u32.u64 %0, t; }" : "=r"(a) : "l"(p));
    return a;
}
__device__ __forceinline__ void cp16(uint32_t s, const void* g) {
    asm volatile("cp.async.cg.shared.global [%0], [%1], 16;" :: "r"(s), "l"(g) : "memory");
}
__device__ __forceinline__ void cp_commit() { asm volatile("cp.async.commit_group;" ::: "memory"); }
__device__ __forceinline__ void cp_wait1()  { asm volatile("cp.async.wait_group 1;" ::: "memory"); }
__device__ __forceinline__ void cp_wait0()  { asm volatile("cp.async.wait_group 0;" ::: "memory"); }

__device__ __forceinline__ void ldmx4(uint32_t& r0, uint32_t& r1, uint32_t& r2, uint32_t& r3,
                                      uint32_t addr)
{
    asm volatile("ldmatrix.sync.aligned.m8n8.x4.shared.b16 {%0,%1,%2,%3}, [%4];"
        : "=r"(r0), "=r"(r1), "=r"(r2), "=r"(r3) : "r"(addr));
}

__device__ __forceinline__ void mma_bf16(float* d,
    uint32_t a0, uint32_t a1, uint32_t a2, uint32_t a3, uint32_t b0, uint32_t b1)
{
    asm volatile("mma.sync.aligned.m16n8k16.row.col.f32.bf16.bf16.f32 "
        "{%0,%1,%2,%3}, {%4,%5,%6,%7}, {%8,%9}, {%0,%1,%2,%3};"
        : "+f"(d[0]), "+f"(d[1]), "+f"(d[2]), "+f"(d[3])
        : "r"(a0), "r"(a1), "r"(a2), "r"(a3), "r"(b0), "r"(b1));
}

__device__ __forceinline__ void split8(const float* x, uint4& hv, uint4& lv) {
    unsigned hs[8], ls[8];
#pragma unroll
    for (int i = 0; i < 8; i++) {
        __nv_bfloat16 h = __float2bfloat16(x[i]);
        float hf = __bfloat162float(h);
        __nv_bfloat16 l = __float2bfloat16(x[i] - hf);
        hs[i] = (unsigned)__bfloat16_as_ushort(h);
        ls[i] = (unsigned)__bfloat16_as_ushort(l);
    }
    hv.x = hs[0] | (hs[1] << 16); hv.y = hs[2] | (hs[3] << 16);
    hv.z = hs[4] | (hs[5] << 16); hv.w = hs[6] | (hs[7] << 16);
    lv.x = ls[0] | (ls[1] << 16); lv.y = ls[2] | (ls[3] << 16);
    lv.z = ls[4] | (ls[5] << 16); lv.w = ls[6] | (ls[7] << 16);
}

// ---------------- convert A: fp32 [NB,K] -> A' bf16 [NB, 3K] = [Ah|Al|Ah] ----------------
__global__ __launch_bounds__(256) void convert_A(
    const float* __restrict__ A, u16* __restrict__ P, int K)
{
    int CPR = K >> 3;
    int id = blockIdx.x * 256 + threadIdx.x;
    if (id >= NB * CPR) return;
    int r = id / CPR, c8 = id - r * CPR;
    float x[8];
    *(float4*)&x[0] = *(const float4*)&A[(size_t)r * K + c8 * 8];
    *(float4*)&x[4] = *(const float4*)&A[(size_t)r * K + c8 * 8 + 4];
    uint4 hv, lv;
    split8(x, hv, lv);
    int K3 = 3 * K;
    size_t base = (size_t)r * K3 + c8 * 8;
    *(uint4*)&P[base]         = hv;
    *(uint4*)&P[base + K]     = lv;
    *(uint4*)&P[base + 2 * K] = hv;
}

// ---------------- convert B: W fp32 [K,N] -> B' bf16 [N, 3K] = [Bh|Bh|Bl] ----------------
__global__ __launch_bounds__(256) void convert_B(
    const float* __restrict__ W, u16* __restrict__ P, int K, int N)
{
    __shared__ float ts[64][68];
    int n0 = blockIdx.x * 64, k0 = blockIdx.y * 64;
#pragma unroll
    for (int t = 0; t < 4; t++) {
        int i = threadIdx.x + t * 256;
        int row = i >> 4, q = i & 15;
        *(float4*)&ts[row][q * 4] = *(const float4*)&W[(size_t)(k0 + row) * N + n0 + q * 4];
    }
    __syncthreads();
    int K3 = 3 * K;
#pragma unroll
    for (int t = 0; t < 2; t++) {
        int s = threadIdx.x + t * 256;
        int n = s >> 3, c8 = s & 7;
        float x[8];
#pragma unroll
        for (int i = 0; i < 8; i++) x[i] = ts[c8 * 8 + i][n];
        uint4 hv, lv;
        split8(x, hv, lv);
        size_t base = (size_t)(n0 + n) * K3 + k0 + c8 * 8;
        *(uint4*)&P[base]         = hv;
        *(uint4*)&P[base + K]     = hv;
        *(uint4*)&P[base + 2 * K] = lv;
    }
}

// ---------------- bf16 mma.sync GEMM: CTA 128x128, warp 32x64, BK=32, ldmatrix ----------------
#define PADK 40   // bf16 row stride in SMEM; 80B row stride -> 16B-aligned ldmatrix rows

__global__ __launch_bounds__(256, 2) void gemm_mma(
    const u16* __restrict__ A, const u16* __restrict__ B,
    const float* __restrict__ bias, int K3, int relu,
    float* __restrict__ outF, int ldF, u16* __restrict__ outP)
{
    __shared__ u16 As[2][128 * PADK];
    __shared__ u16 Bs[2][128 * PADK];
    __shared__ float bias_s[128];

    const int tid = threadIdx.x;
    const int m0 = blockIdx.y * 128, n0 = blockIdx.x * 128;
    const int Nfull = gridDim.x * 128;
    const int lane = tid & 31, wid = tid >> 5;
    const int g = lane >> 2, tig = lane & 3;
    const int wm = (wid & 3) * 32, wn = (wid >> 2) * 64;
    const int lrow = ((lane >> 3) & 1) * 8 + (lane & 7);
    const int lcolm = (lane >> 4) * 8;

    if (tid < 128) bias_s[tid] = bias ? bias[n0 + tid] : 0.0f;

    const u16* Ag = A + (size_t)m0 * K3;
    const u16* Bg = B + (size_t)n0 * K3;

    float acc[2][8][4];
#pragma unroll
    for (int mf = 0; mf < 2; mf++)
#pragma unroll
        for (int nf = 0; nf < 8; nf++)
#pragma unroll
            for (int q = 0; q < 4; q++) acc[mf][nf][q] = 0.0f;

    const int nchunk = K3 >> 5;
    const int lr = (tid >> 2);
    const int lc = (tid & 3) * 8;

    // prefetch chunk 0
    {
#pragma unroll
        for (int p = 0; p < 2; p++) {
            int r = lr + p * 64;
            cp16(smem_u32(&As[0][r * PADK + lc]), Ag + (size_t)r * K3 + lc);
            cp16(smem_u32(&Bs[0][r * PADK + lc]), Bg + (size_t)r * K3 + lc);
        }
        cp_commit();
    }

    for (int kc = 0; kc < nchunk; kc++) {
        if (kc + 1 < nchunk) {
            int k0 = (kc + 1) << 5;
            int buf = (kc + 1) & 1;
#pragma unroll
            for (int p = 0; p < 2; p++) {
                int r = lr + p * 64;
                cp16(smem_u32(&As[buf][r * PADK + lc]), Ag + (size_t)r * K3 + k0 + lc);
                cp16(smem_u32(&Bs[buf][r * PADK + lc]), Bg + (size_t)r * K3 + k0 + lc);
            }
            cp_commit();
            cp_wait1();
        } else {
            cp_wait0();
        }
        __syncthreads();

        const int buf = kc & 1;
#pragma unroll
        for (int ks = 0; ks < 2; ks++) {
            const int kk = (ks << 4) + lcolm;
            uint32_t bfr[8][2];
#pragma unroll
            for (int np = 0; np < 4; np++) {
                uint32_t r0, r1, r2, r3;
                ldmx4(r0, r1, r2, r3,
                      smem_u32(&Bs[buf][(wn + np * 16 + lrow) * PADK + kk]));
                bfr[np * 2][0] = r0; bfr[np * 2 + 1][0] = r1;
                bfr[np * 2][1] = r2; bfr[np * 2 + 1][1] = r3;
            }
#pragma unroll
            for (int mf = 0; mf < 2; mf++) {
                uint32_t a0, a1, a2, a3;
                ldmx4(a0, a1, a2, a3,
                      smem_u32(&As[buf][(wm + mf * 16 + lrow) * PADK + kk]));
#pragma unroll
                for (int nf = 0; nf < 8; nf++)
                    mma_bf16(acc[mf][nf], a0, a1, a2, a3, bfr[nf][0], bfr[nf][1]);
            }
        }
        __syncthreads();
    }

    // epilogue: bias + relu; optional fp32 out; optional next-layer A' panel [M, 3N] = [Ah|Al|Ah]
    const int K3n = 3 * Nfull;
#pragma unroll
    for (int mf = 0; mf < 2; mf++) {
#pragma unroll
        for (int hrow = 0; hrow < 2; hrow++) {
            int row = m0 + wm + mf * 16 + g + hrow * 8;
#pragma unroll
            for (int nf = 0; nf < 8; nf++) {
                int cl = wn + nf * 8 + tig * 2;
                float v0 = acc[mf][nf][hrow * 2 + 0] + bias_s[cl];
                float v1 = acc[mf][nf][hrow * 2 + 1] + bias_s[cl + 1];
                if (relu) { v0 = fmaxf(v0, 0.0f); v1 = fmaxf(v1, 0.0f); }
                int col = n0 + cl;
                if (outF)
                    *(float2*)&outF[(size_t)row * ldF + col] = make_float2(v0, v1);
                if (outP) {
                    __nv_bfloat16 h0 = __float2bfloat16(v0), h1 = __float2bfloat16(v1);
                    float l0 = v0 - __bfloat162float(h0);
                    float l1 = v1 - __bfloat162float(h1);
                    __nv_bfloat16 g0 = __float2bfloat16(l0), g1 = __float2bfloat16(l1);
                    uint32_t hp = (uint32_t)__bfloat16_as_ushort(h0) |
                                  ((uint32_t)__bfloat16_as_ushort(h1) << 16);
                    uint32_t lp = (uint32_t)__bfloat16_as_ushort(g0) |
                                  ((uint32_t)__bfloat16_as_ushort(g1) << 16);
                    size_t base = (size_t)row * K3n + col;
                    *(uint32_t*)&outP[base]             = hp;
                    *(uint32_t*)&outP[base + Nfull]     = lp;
                    *(uint32_t*)&outP[base + 2 * Nfull] = hp;
                }
            }
        }
    }
}

// ---------------- packed f32x2 helpers ----------------
__device__ __forceinline__ u64 fma2_u64(u64 a, u64 b, u64 c)
{
    u64 r;
    asm("fma.rn.f32x2 %0, %1, %2, %3;" : "=l"(r) : "l"(a), "l"(b), "l"(c));
    return r;
}
__device__ __forceinline__ u64 add2_u64(u64 a, u64 b)
{
    u64 r;
    asm("add.rn.f32x2 %0, %1, %2;" : "=l"(r) : "l"(a), "l"(b));
    return r;
}

// ---------------- minibatch discrimination (symmetric, register-blocked R=4) ----------------
// 4 tiles of 512 rows; 10 tile-pairs (ti<=tj):
//   pair 0-3: (0,0),(0,1),(0,2),(0,3)   pair 4-6: (1,1),(1,2),(1,3)  [tj = pair-3]
//   pair 7-8: (2,2),(2,3)               pair 9:   (3,3)
__global__ __launch_bounds__(128) void pairwise_sym(
    const float* __restrict__ Ms, float* __restrict__ outT)
{
    const int pair = blockIdx.x;   // 0..9
    const int b = blockIdx.y;
    int ti, tj;
    if (pair < 4)      { ti = 0; tj = pair; }
    else if (pair < 7) { ti = 1; tj = pair - 3; }   // FIX (R6 bug): was pair-2 -> tj up to 4 (OOB)
    else if (pair < 9) { ti = 2; tj = pair - 5; }
    else               { ti = 3; tj = 3; }
    const bool diag = (ti == tj);

    const int t = threadIdx.x, lane = t & 31, wid = t >> 5;
    const u64 NEG1x2 = 0xBF800000BF800000ull;
    const u64 ABSM   = 0x7FFFFFFF7FFFFFFFull;

    __shared__ u64  sj2[8][512];    // [c-pair][j]  32 KB
    __shared__ float sacc[4][512];  // per-warp transpose accumulators  8 KB

    // load j-tile into pair-packed shared
#pragma unroll
    for (int rb = 0; rb < 4; rb++) {
        int j = rb * 128 + t;
        const float4* src = (const float4*)&Ms[(size_t)(tj * 512 + j) * 2048 + b * 16];
#pragma unroll
        for (int q = 0; q < 4; q++) {
            float4 v = src[q];
            sj2[q * 2 + 0][j] = (u64)__float_as_uint(v.x) | ((u64)__float_as_uint(v.y) << 32);
            sj2[q * 2 + 1][j] = (u64)__float_as_uint(v.z) | ((u64)__float_as_uint(v.w) << 32);
        }
    }
#pragma unroll
    for (int k = t; k < 4 * 512; k += 128) ((float*)sacc)[k] = 0.0f;

    // load mi rows into registers
    u64 mi[4][8];
#pragma unroll
    for (int r = 0; r < 4; r++) {
        const float4* src = (const float4*)&Ms[(size_t)(ti * 512 + r * 128 + t) * 2048 + b * 16];
#pragma unroll
        for (int q = 0; q < 4; q++) {
            float4 v = src[q];
            mi[r][q * 2 + 0] = (u64)__float_as_uint(v.x) | ((u64)__float_as_uint(v.y) << 32);
            mi[r][q * 2 + 1] = (u64)__float_as_uint(v.z) | ((u64)__float_as_uint(v.w) << 32);
        }
    }
    float acc[4] = {0.0f, 0.0f, 0.0f, 0.0f};
    __syncthreads();

    for (int s = 0; s < 512; s++) {
        int j = (lane + s) & 511;
        u64 mj[8];
#pragma unroll
        for (int p = 0; p < 8; p++) mj[p] = sj2[p][j];
        float esum = 0.0f;
#pragma unroll
        for (int r = 0; r < 4; r++) {
            u64 a2 = fma2_u64(mj[0], NEG1x2, mi[r][0]) & ABSM;
#pragma unroll
            for (int p = 1; p < 8; p++) {
                u64 d = fma2_u64(mj[p], NEG1x2, mi[r][p]) & ABSM;
                a2 = add2_u64(a2, d);
            }
            float lo = __uint_as_float((unsigned)(a2 & 0xffffffffu));
            float hi = __uint_as_float((unsigned)(a2 >> 32));
            float e = __expf(-(lo + hi));
            acc[r] += e;
            esum += e;
        }
        if (!diag) sacc[wid][j] += esum;
    }
    __syncthreads();

#pragma unroll
    for (int r = 0; r < 4; r++)
        atomicAdd(&outT[(size_t)(ti * 512 + r * 128 + t) * DB + b], acc[r]);
    if (!diag) {
#pragma unroll
        for (int j = t; j < 512; j += 128) {
            float v = sacc[0][j] + sacc[1][j] + sacc[2][j] + sacc[3][j];
            atomicAdd(&outT[(size_t)(tj * 512 + j) * DB + b], v);
        }
    }
}

// ---------------- final logits ----------------
__global__ __launch_bounds__(256) void final_kernel(
    const float* __restrict__ feature, const float* __restrict__ outT,
    const float* __restrict__ Wo, const float* __restrict__ bo,
    float* __restrict__ out)
{
    const int warp = threadIdx.x >> 5;
    const int lane = threadIdx.x & 31;
    const int row = blockIdx.x * 8 + warp;
    if (row >= NB) return;

    float s = 0.0f;
#pragma unroll
    for (int h = lane; h < H; h += 32)
        s = fmaf(feature[(size_t)row * H + h], Wo[h], s);
#pragma unroll
    for (int c = lane; c < DB; c += 32)
        s = fmaf(outT[(size_t)row * DB + c], Wo[H + c], s);
#pragma unroll
    for (int o = 16; o > 0; o >>= 1)
        s += __shfl_xor_sync(0xffffffffu, s, o);
    if (lane == 0) {
        float v = s + bo[0];
        out[row] = 1.0f / (1.0f + __expf(-v));
    }
}

// ---------------- launch ----------------
extern "C" void kernel_launch(void* const* d_in, const int* in_sizes, int n_in,
                              void* d_out, int out_size)
{
    const float* input = (const float*)d_in[0];
    const float* W1 = (const float*)d_in[1];
    const float* b1 = (const float*)d_in[2];
    const float* W2 = (const float*)d_in[3];
    const float* b2 = (const float*)d_in[4];
    const float* Wh = (const float*)d_in[5];
    const float* bh = (const float*)d_in[6];
    const float* W3 = (const float*)d_in[7];
    const float* b3 = (const float*)d_in[8];
    const float* W4 = (const float*)d_in[9];
    const float* b4 = (const float*)d_in[10];
    const float* Wo = (const float*)d_in[11];
    const float* bo = (const float*)d_in[12];
    const float* T  = (const float*)d_in[13];

    float* out = (float*)d_out;
    float* feature = out;
    float* logits = out + (size_t)NB * H;

    u16 *A0, *A1, *A2, *A3, *A4, *A5, *B1, *B2, *BHp, *B3p, *B4p, *B6;
    float *Ms, *oT;
    cudaGetSymbolAddress((void**)&A0, g_A0);
    cudaGetSymbolAddress((void**)&A1, g_A1);
    cudaGetSymbolAddress((void**)&A2, g_A2);
    cudaGetSymbolAddress((void**)&A3, g_A3);
    cudaGetSymbolAddress((void**)&A4, g_A4);
    cudaGetSymbolAddress((void**)&A5, g_A5);
    cudaGetSymbolAddress((void**)&B1, g_B1);
    cudaGetSymbolAddress((void**)&B2, g_B2);
    cudaGetSymbolAddress((void**)&BHp, g_BH);
    cudaGetSymbolAddress((void**)&B3p, g_B3);
    cudaGetSymbolAddress((void**)&B4p, g_B4);
    cudaGetSymbolAddress((void**)&B6, g_B6);
    cudaGetSymbolAddress((void**)&Ms, g_Ms);
    cudaGetSymbolAddress((void**)&oT, g_outT);

    // conversions to bf16x3 panels
    convert_A<<<(NB * (512 / 8) + 255) / 256, 256>>>(input, A0, 512);
    convert_B<<<dim3(1024 / 64, 512 / 64),  256>>>(W1, B1, 512, 1024);
    convert_B<<<dim3(1536 / 64, 1024 / 64), 256>>>(W2, B2, 1024, 1536);
    convert_B<<<dim3(1536 / 64, 1536 / 64), 256>>>(Wh, BHp, 1536, 1536);
    convert_B<<<dim3(1024 / 64, 1536 / 64), 256>>>(W3, B3p, 1536, 1024);
    convert_B<<<dim3(512 / 64, 1024 / 64),  256>>>(W4, B4p, 1024, 512);
    convert_B<<<dim3(2048 / 64, 512 / 64),  256>>>(T, B6, 512, 2048);

    // GEMM chain on mma.sync bf16 (K' = 3K), epilogues emit next-layer panels
    gemm_mma<<<dim3(8, 16),  256>>>(A0, B1,  b1, 1536, 1, nullptr, 0,    A1);
    gemm_mma<<<dim3(12, 16), 256>>>(A1, B2,  b2, 3072, 1, nullptr, 0,    A2);
    gemm_mma<<<dim3(12, 16), 256>>>(A2, BHp, bh, 4608, 1, nullptr, 0,    A3);
    gemm_mma<<<dim3(8, 16),  256>>>(A3, B3p, b3, 4608, 1, nullptr, 0,    A4);
    gemm_mma<<<dim3(4, 16),  256>>>(A4, B4p, b4, 3072, 1, feature, 512,  A5);
    gemm_mma<<<dim3(16, 16), 256>>>(A5, B6,  nullptr, 1536, 0, Ms, 2048, nullptr);

    // minibatch discrimination (symmetric) + logits
    cudaMemsetAsync(oT, 0, (size_t)NB * DB * sizeof(float), 0);
    pairwise_sym<<<dim3(10, DB), 128>>>(Ms, oT);
    final_kernel<<<NB / 8, 256>>>(feature, oT, Wo, bo, logits);
}

// round 10
// speedup vs baseline: 1.6018x; 1.0119x over previous
#include <cuda_runtime.h>
#include <cuda_bf16.h>
#include <cstdint>

typedef unsigned short u16;
typedef unsigned long long u64;

#define H 512
#define DB 128
#define DC 16
#define NB 2048

// ---------------- scratch panels (bf16 x3 split, K' = 3K concatenation) ----------------
// A' panels: [M, 3K] row-major = [Ah | Al | Ah]
__device__ __align__(16) u16 g_A0[2048 * 1536];
__device__ __align__(16) u16 g_A1[2048 * 3072];
__device__ __align__(16) u16 g_A2[2048 * 4608];
__device__ __align__(16) u16 g_A3[2048 * 4608];
__device__ __align__(16) u16 g_A4[2048 * 3072];
__device__ __align__(16) u16 g_A5[2048 * 1536];
// B' panels: [N, 3K] row-major (k contiguous) = [Bh | Bh | Bl]
__device__ __align__(16) u16 g_B1[1024 * 1536];
__device__ __align__(16) u16 g_B2[1536 * 3072];
__device__ __align__(16) u16 g_BH[1536 * 4608];
__device__ __align__(16) u16 g_B3[1024 * 4608];
__device__ __align__(16) u16 g_B4[512  * 3072];
__device__ __align__(16) u16 g_B6[2048 * 1536];
__device__ __align__(16) float g_Ms[NB * DB * DC];
__device__ __align__(16) float g_outT[NB * DB];

// ---------------- helpers ----------------
__device__ __forceinline__ uint32_t smem_u32(const void* p) {
    uint32_t a;
    asm("{ .reg .u64 t; cvta.to.shared.u64 t, %1; cvt.u32.u64 %0, t; }" : "=r"(a) : "l"(p));
    return a;
}
__device__ __forceinline__ void cp16(uint32_t s, const void* g) {
    asm volatile("cp.async.cg.shared.global [%0], [%1], 16;" :: "r"(s), "l"(g) : "memory");
}
__device__ __forceinline__ void cp_commit() { asm volatile("cp.async.commit_group;" ::: "memory"); }
__device__ __forceinline__ void cp_wait1()  { asm volatile("cp.async.wait_group 1;" ::: "memory"); }
__device__ __forceinline__ void cp_wait0()  { asm volatile("cp.async.wait_group 0;" ::: "memory"); }

__device__ __forceinline__ void ldmx4(uint32_t& r0, uint32_t& r1, uint32_t& r2, uint32_t& r3,
                                      uint32_t addr)
{
    asm volatile("ldmatrix.sync.aligned.m8n8.x4.shared.b16 {%0,%1,%2,%3}, [%4];"
        : "=r"(r0), "=r"(r1), "=r"(r2), "=r"(r3) : "r"(addr));
}

__device__ __forceinline__ void mma_bf16(float* d,
    uint32_t a0, uint32_t a1, uint32_t a2, uint32_t a3, uint32_t b0, uint32_t b1)
{
    asm volatile("mma.sync.aligned.m16n8k16.row.col.f32.bf16.bf16.f32 "
        "{%0,%1,%2,%3}, {%4,%5,%6,%7}, {%8,%9}, {%0,%1,%2,%3};"
        : "+f"(d[0]), "+f"(d[1]), "+f"(d[2]), "+f"(d[3])
        : "r"(a0), "r"(a1), "r"(a2), "r"(a3), "r"(b0), "r"(b1));
}

__device__ __forceinline__ void split8(const float* x, uint4& hv, uint4& lv) {
    unsigned hs[8], ls[8];
#pragma unroll
    for (int i = 0; i < 8; i++) {
        __nv_bfloat16 h = __float2bfloat16(x[i]);
        float hf = __bfloat162float(h);
        __nv_bfloat16 l = __float2bfloat16(x[i] - hf);
        hs[i] = (unsigned)__bfloat16_as_ushort(h);
        ls[i] = (unsigned)__bfloat16_as_ushort(l);
    }
    hv.x = hs[0] | (hs[1] << 16); hv.y = hs[2] | (hs[3] << 16);
    hv.z = hs[4] | (hs[5] << 16); hv.w = hs[6] | (hs[7] << 16);
    lv.x = ls[0] | (ls[1] << 16); lv.y = ls[2] | (ls[3] << 16);
    lv.z = ls[4] | (ls[5] << 16); lv.w = ls[6] | (ls[7] << 16);
}

// ---------------- convert A: fp32 [NB,K] -> A' bf16 [NB, 3K] = [Ah|Al|Ah] ----------------
__global__ __launch_bounds__(256) void convert_A(
    const float* __restrict__ A, u16* __restrict__ P, int K)
{
    int CPR = K >> 3;
    int id = blockIdx.x * 256 + threadIdx.x;
    if (id >= NB * CPR) return;
    int r = id / CPR, c8 = id - r * CPR;
    float x[8];
    *(float4*)&x[0] = *(const float4*)&A[(size_t)r * K + c8 * 8];
    *(float4*)&x[4] = *(const float4*)&A[(size_t)r * K + c8 * 8 + 4];
    uint4 hv, lv;
    split8(x, hv, lv);
    int K3 = 3 * K;
    size_t base = (size_t)r * K3 + c8 * 8;
    *(uint4*)&P[base]         = hv;
    *(uint4*)&P[base + K]     = lv;
    *(uint4*)&P[base + 2 * K] = hv;
}

// ---------------- convert B: W fp32 [K,N] -> B' bf16 [N, 3K] = [Bh|Bh|Bl] ----------------
__global__ __launch_bounds__(256) void convert_B(
    const float* __restrict__ W, u16* __restrict__ P, int K, int N)
{
    __shared__ float ts[64][68];
    int n0 = blockIdx.x * 64, k0 = blockIdx.y * 64;
#pragma unroll
    for (int t = 0; t < 4; t++) {
        int i = threadIdx.x + t * 256;
        int row = i >> 4, q = i & 15;
        *(float4*)&ts[row][q * 4] = *(const float4*)&W[(size_t)(k0 + row) * N + n0 + q * 4];
    }
    __syncthreads();
    int K3 = 3 * K;
#pragma unroll
    for (int t = 0; t < 2; t++) {
        int s = threadIdx.x + t * 256;
        int n = s >> 3, c8 = s & 7;
        float x[8];
#pragma unroll
        for (int i = 0; i < 8; i++) x[i] = ts[c8 * 8 + i][n];
        uint4 hv, lv;
        split8(x, hv, lv);
        size_t base = (size_t)(n0 + n) * K3 + k0 + c8 * 8;
        *(uint4*)&P[base]         = hv;
        *(uint4*)&P[base + K]     = hv;
        *(uint4*)&P[base + 2 * K] = lv;
    }
}

// ---------------- bf16 mma.sync GEMM: CTA 128x128, warp 32x64, BK=32 ----------------
// 3-stage cp.async ring, ONE __syncthreads per chunk. Dynamic smem:
//   stage s (s=0..2): As at s*10240 (5120 u16), Bs at s*10240+5120 (5120 u16)
//   bias floats at u16-offset 30720. Total 61952 bytes.
#define PADK 40
#define STG_ELEMS 10240

__global__ __launch_bounds__(256, 2) void gemm_mma(
    const u16* __restrict__ A, const u16* __restrict__ B,
    const float* __restrict__ bias, int K3, int relu,
    float* __restrict__ outF, int ldF, u16* __restrict__ outP)
{
    extern __shared__ u16 dsm[];
    float* bias_s = (float*)(dsm + 3 * STG_ELEMS);

    const int tid = threadIdx.x;
    const int m0 = blockIdx.y * 128, n0 = blockIdx.x * 128;
    const int Nfull = gridDim.x * 128;
    const int lane = tid & 31, wid = tid >> 5;
    const int g = lane >> 2, tig = lane & 3;
    const int wm = (wid & 3) * 32, wn = (wid >> 2) * 64;
    const int lrow = ((lane >> 3) & 1) * 8 + (lane & 7);
    const int lcolm = (lane >> 4) * 8;

    if (tid < 128) bias_s[tid] = bias ? bias[n0 + tid] : 0.0f;

    const u16* Ag = A + (size_t)m0 * K3;
    const u16* Bg = B + (size_t)n0 * K3;

    float acc[2][8][4];
#pragma unroll
    for (int mf = 0; mf < 2; mf++)
#pragma unroll
        for (int nf = 0; nf < 8; nf++)
#pragma unroll
            for (int q = 0; q < 4; q++) acc[mf][nf][q] = 0.0f;

    const int nchunk = K3 >> 5;
    const int lr = (tid >> 2);
    const int lc = (tid & 3) * 8;

    // prefetch chunks 0,1 into stages 0,1
#pragma unroll
    for (int pf = 0; pf < 2; pf++) {
        u16* As = dsm + pf * STG_ELEMS;
        u16* Bs = As + 5120;
        int k0 = pf << 5;
#pragma unroll
        for (int p = 0; p < 2; p++) {
            int r = lr + p * 64;
            cp16(smem_u32(&As[r * PADK + lc]), Ag + (size_t)r * K3 + k0 + lc);
            cp16(smem_u32(&Bs[r * PADK + lc]), Bg + (size_t)r * K3 + k0 + lc);
        }
        cp_commit();
    }

    int sc = 0;   // compute stage for chunk kc
    int si = 2;   // issue stage for chunk kc+2
    for (int kc = 0; kc < nchunk; kc++) {
        if (kc + 1 < nchunk) cp_wait1(); else cp_wait0();
        __syncthreads();

        if (kc + 2 < nchunk) {
            u16* As = dsm + si * STG_ELEMS;
            u16* Bs = As + 5120;
            int k0 = (kc + 2) << 5;
#pragma unroll
            for (int p = 0; p < 2; p++) {
                int r = lr + p * 64;
                cp16(smem_u32(&As[r * PADK + lc]), Ag + (size_t)r * K3 + k0 + lc);
                cp16(smem_u32(&Bs[r * PADK + lc]), Bg + (size_t)r * K3 + k0 + lc);
            }
            cp_commit();
        }

        const u16* Asb = dsm + sc * STG_ELEMS;
        const u16* Bsb = Asb + 5120;
#pragma unroll
        for (int ks = 0; ks < 2; ks++) {
            const int kk = (ks << 4) + lcolm;
            uint32_t bfr[8][2];
#pragma unroll
            for (int np = 0; np < 4; np++) {
                uint32_t r0, r1, r2, r3;
                ldmx4(r0, r1, r2, r3,
                      smem_u32(&Bsb[(wn + np * 16 + lrow) * PADK + kk]));
                bfr[np * 2][0] = r0; bfr[np * 2 + 1][0] = r1;
                bfr[np * 2][1] = r2; bfr[np * 2 + 1][1] = r3;
            }
#pragma unroll
            for (int mf = 0; mf < 2; mf++) {
                uint32_t a0, a1, a2, a3;
                ldmx4(a0, a1, a2, a3,
                      smem_u32(&Asb[(wm + mf * 16 + lrow) * PADK + kk]));
#pragma unroll
                for (int nf = 0; nf < 8; nf++)
                    mma_bf16(acc[mf][nf], a0, a1, a2, a3, bfr[nf][0], bfr[nf][1]);
            }
        }

        sc = (sc == 2) ? 0 : sc + 1;
        si = (si == 2) ? 0 : si + 1;
    }

    // epilogue: bias + relu; optional fp32 out; optional next-layer A' panel [M, 3N] = [Ah|Al|Ah]
    const int K3n = 3 * Nfull;
#pragma unroll
    for (int mf = 0; mf < 2; mf++) {
#pragma unroll
        for (int hrow = 0; hrow < 2; hrow++) {
            int row = m0 + wm + mf * 16 + g + hrow * 8;
#pragma unroll
            for (int nf = 0; nf < 8; nf++) {
                int cl = wn + nf * 8 + tig * 2;
                float v0 = acc[mf][nf][hrow * 2 + 0] + bias_s[cl];
                float v1 = acc[mf][nf][hrow * 2 + 1] + bias_s[cl + 1];
                if (relu) { v0 = fmaxf(v0, 0.0f); v1 = fmaxf(v1, 0.0f); }
                int col = n0 + cl;
                if (outF)
                    *(float2*)&outF[(size_t)row * ldF + col] = make_float2(v0, v1);
                if (outP) {
                    __nv_bfloat16 h0 = __float2bfloat16(v0), h1 = __float2bfloat16(v1);
                    float l0 = v0 - __bfloat162float(h0);
                    float l1 = v1 - __bfloat162float(h1);
                    __nv_bfloat16 g0 = __float2bfloat16(l0), g1 = __float2bfloat16(l1);
                    uint32_t hp = (uint32_t)__bfloat16_as_ushort(h0) |
                                  ((uint32_t)__bfloat16_as_ushort(h1) << 16);
                    uint32_t lp = (uint32_t)__bfloat16_as_ushort(g0) |
                                  ((uint32_t)__bfloat16_as_ushort(g1) << 16);
                    size_t base = (size_t)row * K3n + col;
                    *(uint32_t*)&outP[base]             = hp;
                    *(uint32_t*)&outP[base + Nfull]     = lp;
                    *(uint32_t*)&outP[base + 2 * Nfull] = hp;
                }
            }
        }
    }
}

// ---------------- packed f32x2 helpers ----------------
__device__ __forceinline__ u64 fma2_u64(u64 a, u64 b, u64 c)
{
    u64 r;
    asm("fma.rn.f32x2 %0, %1, %2, %3;" : "=l"(r) : "l"(a), "l"(b), "l"(c));
    return r;
}
__device__ __forceinline__ u64 add2_u64(u64 a, u64 b)
{
    u64 r;
    asm("add.rn.f32x2 %0, %1, %2;" : "=l"(r) : "l"(a), "l"(b));
    return r;
}

// ---------------- minibatch discrimination (symmetric, register-blocked R=4) ----------------
__global__ __launch_bounds__(128) void pairwise_sym(
    const float* __restrict__ Ms, float* __restrict__ outT)
{
    const int pair = blockIdx.x;   // 0..9
    const int b = blockIdx.y;
    int ti, tj;
    if (pair < 4)      { ti = 0; tj = pair; }
    else if (pair < 7) { ti = 1; tj = pair - 3; }
    else if (pair < 9) { ti = 2; tj = pair - 5; }
    else               { ti = 3; tj = 3; }
    const bool diag = (ti == tj);

    const int t = threadIdx.x, lane = t & 31, wid = t >> 5;
    const u64 NEG1x2 = 0xBF800000BF800000ull;
    const u64 ABSM   = 0x7FFFFFFF7FFFFFFFull;

    __shared__ u64  sj2[8][512];
    __shared__ float sacc[4][512];

#pragma unroll
    for (int rb = 0; rb < 4; rb++) {
        int j = rb * 128 + t;
        const float4* src = (const float4*)&Ms[(size_t)(tj * 512 + j) * 2048 + b * 16];
#pragma unroll
        for (int q = 0; q < 4; q++) {
            float4 v = src[q];
            sj2[q * 2 + 0][j] = (u64)__float_as_uint(v.x) | ((u64)__float_as_uint(v.y) << 32);
            sj2[q * 2 + 1][j] = (u64)__float_as_uint(v.z) | ((u64)__float_as_uint(v.w) << 32);
        }
    }
#pragma unroll
    for (int k = t; k < 4 * 512; k += 128) ((float*)sacc)[k] = 0.0f;

    u64 mi[4][8];
#pragma unroll
    for (int r = 0; r < 4; r++) {
        const float4* src = (const float4*)&Ms[(size_t)(ti * 512 + r * 128 + t) * 2048 + b * 16];
#pragma unroll
        for (int q = 0; q < 4; q++) {
            float4 v = src[q];
            mi[r][q * 2 + 0] = (u64)__float_as_uint(v.x) | ((u64)__float_as_uint(v.y) << 32);
            mi[r][q * 2 + 1] = (u64)__float_as_uint(v.z) | ((u64)__float_as_uint(v.w) << 32);
        }
    }
    float acc[4] = {0.0f, 0.0f, 0.0f, 0.0f};
    __syncthreads();

    for (int s = 0; s < 512; s++) {
        int j = (lane + s) & 511;
        u64 mj[8];
#pragma unroll
        for (int p = 0; p < 8; p++) mj[p] = sj2[p][j];
        float esum = 0.0f;
#pragma unroll
        for (int r = 0; r < 4; r++) {
            u64 a2 = fma2_u64(mj[0], NEG1x2, mi[r][0]) & ABSM;
#pragma unroll
            for (int p = 1; p < 8; p++) {
                u64 d = fma2_u64(mj[p], NEG1x2, mi[r][p]) & ABSM;
                a2 = add2_u64(a2, d);
            }
            float lo = __uint_as_float((unsigned)(a2 & 0xffffffffu));
            float hi = __uint_as_float((unsigned)(a2 >> 32));
            float e = __expf(-(lo + hi));
            acc[r] += e;
            esum += e;
        }
        if (!diag) sacc[wid][j] += esum;
    }
    __syncthreads();

#pragma unroll
    for (int r = 0; r < 4; r++)
        atomicAdd(&outT[(size_t)(ti * 512 + r * 128 + t) * DB + b], acc[r]);
    if (!diag) {
#pragma unroll
        for (int j = t; j < 512; j += 128) {
            float v = sacc[0][j] + sacc[1][j] + sacc[2][j] + sacc[3][j];
            atomicAdd(&outT[(size_t)(tj * 512 + j) * DB + b], v);
        }
    }
}

// ---------------- final logits ----------------
__global__ __launch_bounds__(256) void final_kernel(
    const float* __restrict__ feature, const float* __restrict__ outT,
    const float* __restrict__ Wo, const float* __restrict__ bo,
    float* __restrict__ out)
{
    const int warp = threadIdx.x >> 5;
    const int lane = threadIdx.x & 31;
    const int row = blockIdx.x * 8 + warp;
    if (row >= NB) return;

    float s = 0.0f;
#pragma unroll
    for (int h = lane; h < H; h += 32)
        s = fmaf(feature[(size_t)row * H + h], Wo[h], s);
#pragma unroll
    for (int c = lane; c < DB; c += 32)
        s = fmaf(outT[(size_t)row * DB + c], Wo[H + c], s);
#pragma unroll
    for (int o = 16; o > 0; o >>= 1)
        s += __shfl_xor_sync(0xffffffffu, s, o);
    if (lane == 0) {
        float v = s + bo[0];
        out[row] = 1.0f / (1.0f + __expf(-v));
    }
}

// ---------------- launch ----------------
#define GEMM_SMEM 61952

extern "C" void kernel_launch(void* const* d_in, const int* in_sizes, int n_in,
                              void* d_out, int out_size)
{
    const float* input = (const float*)d_in[0];
    const float* W1 = (const float*)d_in[1];
    const float* b1 = (const float*)d_in[2];
    const float* W2 = (const float*)d_in[3];
    const float* b2 = (const float*)d_in[4];
    const float* Wh = (const float*)d_in[5];
    const float* bh = (const float*)d_in[6];
    const float* W3 = (const float*)d_in[7];
    const float* b3 = (const float*)d_in[8];
    const float* W4 = (const float*)d_in[9];
    const float* b4 = (const float*)d_in[10];
    const float* Wo = (const float*)d_in[11];
    const float* bo = (const float*)d_in[12];
    const float* T  = (const float*)d_in[13];

    float* out = (float*)d_out;
    float* feature = out;
    float* logits = out + (size_t)NB * H;

    u16 *A0, *A1, *A2, *A3, *A4, *A5, *B1, *B2, *BHp, *B3p, *B4p, *B6;
    float *Ms, *oT;
    cudaGetSymbolAddress((void**)&A0, g_A0);
    cudaGetSymbolAddress((void**)&A1, g_A1);
    cudaGetSymbolAddress((void**)&A2, g_A2);
    cudaGetSymbolAddress((void**)&A3, g_A3);
    cudaGetSymbolAddress((void**)&A4, g_A4);
    cudaGetSymbolAddress((void**)&A5, g_A5);
    cudaGetSymbolAddress((void**)&B1, g_B1);
    cudaGetSymbolAddress((void**)&B2, g_B2);
    cudaGetSymbolAddress((void**)&BHp, g_BH);
    cudaGetSymbolAddress((void**)&B3p, g_B3);
    cudaGetSymbolAddress((void**)&B4p, g_B4);
    cudaGetSymbolAddress((void**)&B6, g_B6);
    cudaGetSymbolAddress((void**)&Ms, g_Ms);
    cudaGetSymbolAddress((void**)&oT, g_outT);

    cudaFuncSetAttribute(gemm_mma, cudaFuncAttributeMaxDynamicSharedMemorySize, GEMM_SMEM);

    // Launch order arranged so launch #6 (ncu -s 5 -c 1 capture slot) is gemm L1.
    convert_A<<<(NB * (512 / 8) + 255) / 256, 256>>>(input, A0, 512);              // #1
    convert_B<<<dim3(1024 / 64, 512 / 64),  256>>>(W1, B1, 512, 1024);             // #2
    convert_B<<<dim3(1536 / 64, 1024 / 64), 256>>>(W2, B2, 1024, 1536);            // #3
    convert_B<<<dim3(1536 / 64, 1536 / 64), 256>>>(Wh, BHp, 1536, 1536);           // #4
    convert_B<<<dim3(1024 / 64, 1536 / 64), 256>>>(W3, B3p, 1536, 1024);           // #5
    gemm_mma<<<dim3(8, 16),  256, GEMM_SMEM>>>(A0, B1, b1, 1536, 1, nullptr, 0, A1); // #6 <- profiled
    convert_B<<<dim3(512 / 64, 1024 / 64),  256>>>(W4, B4p, 1024, 512);            // #7
    convert_B<<<dim3(2048 / 64, 512 / 64),  256>>>(T, B6, 512, 2048);              // #8

    gemm_mma<<<dim3(12, 16), 256, GEMM_SMEM>>>(A1, B2,  b2, 3072, 1, nullptr, 0,    A2);
    gemm_mma<<<dim3(12, 16), 256, GEMM_SMEM>>>(A2, BHp, bh, 4608, 1, nullptr, 0,    A3);
    gemm_mma<<<dim3(8, 16),  256, GEMM_SMEM>>>(A3, B3p, b3, 4608, 1, nullptr, 0,    A4);
    gemm_mma<<<dim3(4, 16),  256, GEMM_SMEM>>>(A4, B4p, b4, 3072, 1, feature, 512,  A5);
    gemm_mma<<<dim3(16, 16), 256, GEMM_SMEM>>>(A5, B6,  nullptr, 1536, 0, Ms, 2048, nullptr);

    // minibatch discrimination (symmetric) + logits
    cudaMemsetAsync(oT, 0, (size_t)NB * DB * sizeof(float), 0);
    pairwise_sym<<<dim3(10, DB), 128>>>(Ms, oT);
    final_kernel<<<NB / 8, 256>>>(feature, oT, Wo, bo, logits);
}

// round 12
// speedup vs baseline: 1.6059x; 1.0026x over previous
#include <cuda_runtime.h>
#include <cuda_bf16.h>
#include <cstdint>

typedef unsigned short u16;
typedef unsigned long long u64;

#define H 512
#define DB 128
#define DC 16
#define NB 2048

// ---------------- scratch panels (bf16 x3 split, K' = 3K concatenation) ----------------
// A' panels: [M, 3K] row-major = [Ah | Al | Ah]
__device__ __align__(16) u16 g_A0[2048 * 1536];
__device__ __align__(16) u16 g_A1[2048 * 3072];
__device__ __align__(16) u16 g_A2[2048 * 4608];
__device__ __align__(16) u16 g_A3[2048 * 4608];
__device__ __align__(16) u16 g_A4[2048 * 3072];
__device__ __align__(16) u16 g_A5[2048 * 1536];
// B' panels: [N, 3K] row-major (k contiguous) = [Bh | Bh | Bl]
__device__ __align__(16) u16 g_B1[1024 * 1536];
__device__ __align__(16) u16 g_B2[1536 * 3072];
__device__ __align__(16) u16 g_BH[1536 * 4608];
__device__ __align__(16) u16 g_B3[1024 * 4608];
__device__ __align__(16) u16 g_B4[512  * 3072];
__device__ __align__(16) u16 g_B6[2048 * 1536];
__device__ __align__(16) float g_Ms[NB * DB * DC];
__device__ __align__(16) float g_outT[NB * DB];

// ---------------- helpers ----------------
__device__ __forceinline__ uint32_t smem_u32(const void* p) {
    uint32_t a;
    asm("{ .reg .u64 t; cvta.to.shared.u64 t, %1; cvt.u32.u64 %0, t; }" : "=r"(a) : "l"(p));
    return a;
}
__device__ __forceinline__ void cp16(uint32_t s, const void* g) {
    asm volatile("cp.async.cg.shared.global [%0], [%1], 16;" :: "r"(s), "l"(g) : "memory");
}
__device__ __forceinline__ void cp_commit() { asm volatile("cp.async.commit_group;" ::: "memory"); }
__device__ __forceinline__ void cp_wait1()  { asm volatile("cp.async.wait_group 1;" ::: "memory"); }
__device__ __forceinline__ void cp_wait0()  { asm volatile("cp.async.wait_group 0;" ::: "memory"); }

__device__ __forceinline__ void ldmx4(uint32_t& r0, uint32_t& r1, uint32_t& r2, uint32_t& r3,
                                      uint32_t addr)
{
    asm volatile("ldmatrix.sync.aligned.m8n8.x4.shared.b16 {%0,%1,%2,%3}, [%4];"
        : "=r"(r0), "=r"(r1), "=r"(r2), "=r"(r3) : "r"(addr));
}

__device__ __forceinline__ void mma_bf16(float* d,
    uint32_t a0, uint32_t a1, uint32_t a2, uint32_t a3, uint32_t b0, uint32_t b1)
{
    asm volatile("mma.sync.aligned.m16n8k16.row.col.f32.bf16.bf16.f32 "
        "{%0,%1,%2,%3}, {%4,%5,%6,%7}, {%8,%9}, {%0,%1,%2,%3};"
        : "+f"(d[0]), "+f"(d[1]), "+f"(d[2]), "+f"(d[3])
        : "r"(a0), "r"(a1), "r"(a2), "r"(a3), "r"(b0), "r"(b1));
}

__device__ __forceinline__ void split8(const float* x, uint4& hv, uint4& lv) {
    unsigned hs[8], ls[8];
#pragma unroll
    for (int i = 0; i < 8; i++) {
        __nv_bfloat16 h = __float2bfloat16(x[i]);
        float hf = __bfloat162float(h);
        __nv_bfloat16 l = __float2bfloat16(x[i] - hf);
        hs[i] = (unsigned)__bfloat16_as_ushort(h);
        ls[i] = (unsigned)__bfloat16_as_ushort(l);
    }
    hv.x = hs[0] | (hs[1] << 16); hv.y = hs[2] | (hs[3] << 16);
    hv.z = hs[4] | (hs[5] << 16); hv.w = hs[6] | (hs[7] << 16);
    lv.x = ls[0] | (ls[1] << 16); lv.y = ls[2] | (ls[3] << 16);
    lv.z = ls[4] | (ls[5] << 16); lv.w = ls[6] | (ls[7] << 16);
}

// ---------------- convert A: fp32 [NB,K] -> A' bf16 [NB, 3K] = [Ah|Al|Ah] ----------------
__global__ __launch_bounds__(256) void convert_A(
    const float* __restrict__ A, u16* __restrict__ P, int K)
{
    int CPR = K >> 3;
    int id = blockIdx.x * 256 + threadIdx.x;
    if (id >= NB * CPR) return;
    int r = id / CPR, c8 = id - r * CPR;
    float x[8];
    *(float4*)&x[0] = *(const float4*)&A[(size_t)r * K + c8 * 8];
    *(float4*)&x[4] = *(const float4*)&A[(size_t)r * K + c8 * 8 + 4];
    uint4 hv, lv;
    split8(x, hv, lv);
    int K3 = 3 * K;
    size_t base = (size_t)r * K3 + c8 * 8;
    *(uint4*)&P[base]         = hv;
    *(uint4*)&P[base + K]     = lv;
    *(uint4*)&P[base + 2 * K] = hv;
}

// ---------------- convert B: W fp32 [K,N] -> B' bf16 [N, 3K] = [Bh|Bh|Bl] ----------------
__global__ __launch_bounds__(256) void convert_B(
    const float* __restrict__ W, u16* __restrict__ P, int K, int N)
{
    __shared__ float ts[64][68];
    int n0 = blockIdx.x * 64, k0 = blockIdx.y * 64;
#pragma unroll
    for (int t = 0; t < 4; t++) {
        int i = threadIdx.x + t * 256;
        int row = i >> 4, q = i & 15;
        *(float4*)&ts[row][q * 4] = *(const float4*)&W[(size_t)(k0 + row) * N + n0 + q * 4];
    }
    __syncthreads();
    int K3 = 3 * K;
#pragma unroll
    for (int t = 0; t < 2; t++) {
        int s = threadIdx.x + t * 256;
        int n = s >> 3, c8 = s & 7;
        float x[8];
#pragma unroll
        for (int i = 0; i < 8; i++) x[i] = ts[c8 * 8 + i][n];
        uint4 hv, lv;
        split8(x, hv, lv);
        size_t base = (size_t)(n0 + n) * K3 + k0 + c8 * 8;
        *(uint4*)&P[base]         = hv;
        *(uint4*)&P[base + K]     = hv;
        *(uint4*)&P[base + 2 * K] = lv;
    }
}

// ---------------- bf16 mma.sync GEMM: CTA 128x128, warp 32x64, BK=32 ----------------
// 3-stage cp.async ring, one __syncthreads per chunk. Dynamic smem:
//   stage s: As at s*10240 (5120 u16), Bs at +5120; bias at u16-offset 30720. 61952 B.
#define PADK 40
#define STG_ELEMS 10240

__global__ __launch_bounds__(256, 2) void gemm_mma(
    const u16* __restrict__ A, const u16* __restrict__ B,
    const float* __restrict__ bias, int K3, int relu,
    float* __restrict__ outF, int ldF, u16* __restrict__ outP)
{
    extern __shared__ u16 dsm[];
    float* bias_s = (float*)(dsm + 3 * STG_ELEMS);

    const int tid = threadIdx.x;
    const int m0 = blockIdx.y * 128, n0 = blockIdx.x * 128;
    const int Nfull = gridDim.x * 128;
    const int lane = tid & 31, wid = tid >> 5;
    const int g = lane >> 2, tig = lane & 3;
    const int wm = (wid & 3) * 32, wn = (wid >> 2) * 64;
    const int lrow = ((lane >> 3) & 1) * 8 + (lane & 7);
    const int lcolm = (lane >> 4) * 8;

    if (tid < 128) bias_s[tid] = bias ? bias[n0 + tid] : 0.0f;

    const u16* Ag = A + (size_t)m0 * K3;
    const u16* Bg = B + (size_t)n0 * K3;

    float acc[2][8][4];
#pragma unroll
    for (int mf = 0; mf < 2; mf++)
#pragma unroll
        for (int nf = 0; nf < 8; nf++)
#pragma unroll
            for (int q = 0; q < 4; q++) acc[mf][nf][q] = 0.0f;

    const int nchunk = K3 >> 5;
    const int lr = (tid >> 2);
    const int lc = (tid & 3) * 8;

    // prefetch chunks 0,1 into stages 0,1
#pragma unroll
    for (int pf = 0; pf < 2; pf++) {
        u16* As = dsm + pf * STG_ELEMS;
        u16* Bs = As + 5120;
        int k0 = pf << 5;
#pragma unroll
        for (int p = 0; p < 2; p++) {
            int r = lr + p * 64;
            cp16(smem_u32(&As[r * PADK + lc]), Ag + (size_t)r * K3 + k0 + lc);
            cp16(smem_u32(&Bs[r * PADK + lc]), Bg + (size_t)r * K3 + k0 + lc);
        }
        cp_commit();
    }

    int sc = 0, si = 2;
    for (int kc = 0; kc < nchunk; kc++) {
        if (kc + 1 < nchunk) cp_wait1(); else cp_wait0();
        __syncthreads();

        if (kc + 2 < nchunk) {
            u16* As = dsm + si * STG_ELEMS;
            u16* Bs = As + 5120;
            int k0 = (kc + 2) << 5;
#pragma unroll
            for (int p = 0; p < 2; p++) {
                int r = lr + p * 64;
                cp16(smem_u32(&As[r * PADK + lc]), Ag + (size_t)r * K3 + k0 + lc);
                cp16(smem_u32(&Bs[r * PADK + lc]), Bg + (size_t)r * K3 + k0 + lc);
            }
            cp_commit();
        }

        const u16* Asb = dsm + sc * STG_ELEMS;
        const u16* Bsb = Asb + 5120;
#pragma unroll
        for (int ks = 0; ks < 2; ks++) {
            const int kk = (ks << 4) + lcolm;
            uint32_t bfr[8][2];
#pragma unroll
            for (int np = 0; np < 4; np++) {
                uint32_t r0, r1, r2, r3;
                ldmx4(r0, r1, r2, r3,
                      smem_u32(&Bsb[(wn + np * 16 + lrow) * PADK + kk]));
                bfr[np * 2][0] = r0; bfr[np * 2 + 1][0] = r1;
                bfr[np * 2][1] = r2; bfr[np * 2 + 1][1] = r3;
            }
#pragma unroll
            for (int mf = 0; mf < 2; mf++) {
                uint32_t a0, a1, a2, a3;
                ldmx4(a0, a1, a2, a3,
                      smem_u32(&Asb[(wm + mf * 16 + lrow) * PADK + kk]));
#pragma unroll
                for (int nf = 0; nf < 8; nf++)
                    mma_bf16(acc[mf][nf], a0, a1, a2, a3, bfr[nf][0], bfr[nf][1]);
            }
        }

        sc = (sc == 2) ? 0 : sc + 1;
        si = (si == 2) ? 0 : si + 1;
    }

    // epilogue
    const int K3n = 3 * Nfull;
#pragma unroll
    for (int mf = 0; mf < 2; mf++) {
#pragma unroll
        for (int hrow = 0; hrow < 2; hrow++) {
            int row = m0 + wm + mf * 16 + g + hrow * 8;
#pragma unroll
            for (int nf = 0; nf < 8; nf++) {
                int cl = wn + nf * 8 + tig * 2;
                float v0 = acc[mf][nf][hrow * 2 + 0] + bias_s[cl];
                float v1 = acc[mf][nf][hrow * 2 + 1] + bias_s[cl + 1];
                if (relu) { v0 = fmaxf(v0, 0.0f); v1 = fmaxf(v1, 0.0f); }
                int col = n0 + cl;
                if (outF)
                    *(float2*)&outF[(size_t)row * ldF + col] = make_float2(v0, v1);
                if (outP) {
                    __nv_bfloat16 h0 = __float2bfloat16(v0), h1 = __float2bfloat16(v1);
                    float l0 = v0 - __bfloat162float(h0);
                    float l1 = v1 - __bfloat162float(h1);
                    __nv_bfloat16 g0 = __float2bfloat16(l0), g1 = __float2bfloat16(l1);
                    uint32_t hp = (uint32_t)__bfloat16_as_ushort(h0) |
                                  ((uint32_t)__bfloat16_as_ushort(h1) << 16);
                    uint32_t lp = (uint32_t)__bfloat16_as_ushort(g0) |
                                  ((uint32_t)__bfloat16_as_ushort(g1) << 16);
                    size_t base = (size_t)row * K3n + col;
                    *(uint32_t*)&outP[base]             = hp;
                    *(uint32_t*)&outP[base + Nfull]     = lp;
                    *(uint32_t*)&outP[base + 2 * Nfull] = hp;
                }
            }
        }
    }
}

// ---------------- packed f32x2 helpers ----------------
__device__ __forceinline__ u64 fma2_u64(u64 a, u64 b, u64 c)
{
    u64 r;
    asm("fma.rn.f32x2 %0, %1, %2, %3;" : "=l"(r) : "l"(a), "l"(b), "l"(c));
    return r;
}
__device__ __forceinline__ u64 add2_u64(u64 a, u64 b)
{
    u64 r;
    asm("add.rn.f32x2 %0, %1, %2;" : "=l"(r) : "l"(a), "l"(b));
    return r;
}

// ---------------- minibatch discrimination (symmetric, register-blocked R=4) ----------------
// sj2 packed as [4][512][2] u64 so each j-row's 8 u64 load as 4x LDS.128 (16B stride,
// 8 consecutive lanes span all 32 banks -> conflict-free).
__global__ __launch_bounds__(128) void pairwise_sym(
    const float* __restrict__ Ms, float* __restrict__ outT)
{
    const int pair = blockIdx.x;   // 0..9
    const int b = blockIdx.y;
    int ti, tj;
    if (pair < 4)      { ti = 0; tj = pair; }
    else if (pair < 7) { ti = 1; tj = pair - 3; }
    else if (pair < 9) { ti = 2; tj = pair - 5; }
    else               { ti = 3; tj = 3; }
    const bool diag = (ti == tj);

    const int t = threadIdx.x, lane = t & 31, wid = t >> 5;
    const u64 NEG1x2 = 0xBF800000BF800000ull;
    const u64 ABSM   = 0x7FFFFFFF7FFFFFFFull;

    __shared__ u64  sj2[4][512][2];   // 32 KB, [q][j][pair-in-q]
    __shared__ float sacc[4][512];    // 8 KB

#pragma unroll
    for (int rb = 0; rb < 4; rb++) {
        int j = rb * 128 + t;
        const float4* src = (const float4*)&Ms[(size_t)(tj * 512 + j) * 2048 + b * 16];
#pragma unroll
        for (int q = 0; q < 4; q++) {
            float4 v = src[q];
            sj2[q][j][0] = (u64)__float_as_uint(v.x) | ((u64)__float_as_uint(v.y) << 32);
            sj2[q][j][1] = (u64)__float_as_uint(v.z) | ((u64)__float_as_uint(v.w) << 32);
        }
    }
#pragma unroll
    for (int k = t; k < 4 * 512; k += 128) ((float*)sacc)[k] = 0.0f;

    u64 mi[4][8];
#pragma unroll
    for (int r = 0; r < 4; r++) {
        const float4* src = (const float4*)&Ms[(size_t)(ti * 512 + r * 128 + t) * 2048 + b * 16];
#pragma unroll
        for (int q = 0; q < 4; q++) {
            float4 v = src[q];
            mi[r][q * 2 + 0] = (u64)__float_as_uint(v.x) | ((u64)__float_as_uint(v.y) << 32);
            mi[r][q * 2 + 1] = (u64)__float_as_uint(v.z) | ((u64)__float_as_uint(v.w) << 32);
        }
    }
    float acc[4] = {0.0f, 0.0f, 0.0f, 0.0f};
    __syncthreads();

    for (int s = 0; s < 512; s++) {
        int j = (lane + s) & 511;
        u64 mj[8];
#pragma unroll
        for (int q = 0; q < 4; q++) {
            ulonglong2 v = *(const ulonglong2*)&sj2[q][j][0];
            mj[q * 2 + 0] = v.x;
            mj[q * 2 + 1] = v.y;
        }
        float esum = 0.0f;
#pragma unroll
        for (int r = 0; r < 4; r++) {
            u64 a2 = fma2_u64(mj[0], NEG1x2, mi[r][0]) & ABSM;
#pragma unroll
            for (int p = 1; p < 8; p++) {
                u64 d = fma2_u64(mj[p], NEG1x2, mi[r][p]) & ABSM;
                a2 = add2_u64(a2, d);
            }
            float lo = __uint_as_float((unsigned)(a2 & 0xffffffffu));
            float hi = __uint_as_float((unsigned)(a2 >> 32));
            float e = __expf(-(lo + hi));
            acc[r] += e;
            esum += e;
        }
        if (!diag) sacc[wid][j] += esum;
    }
    __syncthreads();

#pragma unroll
    for (int r = 0; r < 4; r++)
        atomicAdd(&outT[(size_t)(ti * 512 + r * 128 + t) * DB + b], acc[r]);
    if (!diag) {
#pragma unroll
        for (int j = t; j < 512; j += 128) {
            float v = sacc[0][j] + sacc[1][j] + sacc[2][j] + sacc[3][j];
            atomicAdd(&outT[(size_t)(tj * 512 + j) * DB + b], v);
        }
    }
}

// ---------------- final logits ----------------
__global__ __launch_bounds__(256) void final_kernel(
    const float* __restrict__ feature, const float* __restrict__ outT,
    const float* __restrict__ Wo, const float* __restrict__ bo,
    float* __restrict__ out)
{
    const int warp = threadIdx.x >> 5;
    const int lane = threadIdx.x & 31;
    const int row = blockIdx.x * 8 + warp;
    if (row >= NB) return;

    float s = 0.0f;
#pragma unroll
    for (int h = lane; h < H; h += 32)
        s = fmaf(feature[(size_t)row * H + h], Wo[h], s);
#pragma unroll
    for (int c = lane; c < DB; c += 32)
        s = fmaf(outT[(size_t)row * DB + c], Wo[H + c], s);
#pragma unroll
    for (int o = 16; o > 0; o >>= 1)
        s += __shfl_xor_sync(0xffffffffu, s, o);
    if (lane == 0) {
        float v = s + bo[0];
        out[row] = 1.0f / (1.0f + __expf(-v));
    }
}

// ---------------- launch ----------------
#define GEMM_SMEM 61952

extern "C" void kernel_launch(void* const* d_in, const int* in_sizes, int n_in,
                              void* d_out, int out_size)
{
    const float* input = (const float*)d_in[0];
    const float* W1 = (const float*)d_in[1];
    const float* b1 = (const float*)d_in[2];
    const float* W2 = (const float*)d_in[3];
    const float* b2 = (const float*)d_in[4];
    const float* Wh = (const float*)d_in[5];
    const float* bh = (const float*)d_in[6];
    const float* W3 = (const float*)d_in[7];
    const float* b3 = (const float*)d_in[8];
    const float* W4 = (const float*)d_in[9];
    const float* b4 = (const float*)d_in[10];
    const float* Wo = (const float*)d_in[11];
    const float* bo = (const float*)d_in[12];
    const float* T  = (const float*)d_in[13];

    float* out = (float*)d_out;
    float* feature = out;
    float* logits = out + (size_t)NB * H;

    u16 *A0, *A1, *A2, *A3, *A4, *A5, *B1, *B2, *BHp, *B3p, *B4p, *B6;
    float *Ms, *oT;
    cudaGetSymbolAddress((void**)&A0, g_A0);
    cudaGetSymbolAddress((void**)&A1, g_A1);
    cudaGetSymbolAddress((void**)&A2, g_A2);
    cudaGetSymbolAddress((void**)&A3, g_A3);
    cudaGetSymbolAddress((void**)&A4, g_A4);
    cudaGetSymbolAddress((void**)&A5, g_A5);
    cudaGetSymbolAddress((void**)&B1, g_B1);
    cudaGetSymbolAddress((void**)&B2, g_B2);
    cudaGetSymbolAddress((void**)&BHp, g_BH);
    cudaGetSymbolAddress((void**)&B3p, g_B3);
    cudaGetSymbolAddress((void**)&B4p, g_B4);
    cudaGetSymbolAddress((void**)&B6, g_B6);
    cudaGetSymbolAddress((void**)&Ms, g_Ms);
    cudaGetSymbolAddress((void**)&oT, g_outT);

    cudaFuncSetAttribute(gemm_mma, cudaFuncAttributeMaxDynamicSharedMemorySize, GEMM_SMEM);

    // Profiler captures (2 harness pre-launches + skip 3) = MY LAUNCH #4 -> put gemm L1 there.
    convert_A<<<(NB * (512 / 8) + 255) / 256, 256>>>(input, A0, 512);                // #1
    convert_B<<<dim3(1024 / 64, 512 / 64),  256>>>(W1, B1, 512, 1024);               // #2
    convert_B<<<dim3(1536 / 64, 1024 / 64), 256>>>(W2, B2, 1024, 1536);              // #3
    gemm_mma<<<dim3(8, 16), 256, GEMM_SMEM>>>(A0, B1, b1, 1536, 1, nullptr, 0, A1);  // #4 <- profiled
    convert_B<<<dim3(1536 / 64, 1536 / 64), 256>>>(Wh, BHp, 1536, 1536);             // #5
    convert_B<<<dim3(1024 / 64, 1536 / 64), 256>>>(W3, B3p, 1536, 1024);             // #6
    convert_B<<<dim3(512 / 64, 1024 / 64),  256>>>(W4, B4p, 1024, 512);              // #7
    convert_B<<<dim3(2048 / 64, 512 / 64),  256>>>(T, B6, 512, 2048);                // #8

    gemm_mma<<<dim3(12, 16), 256, GEMM_SMEM>>>(A1, B2,  b2, 3072, 1, nullptr, 0,    A2);
    gemm_mma<<<dim3(12, 16), 256, GEMM_SMEM>>>(A2, BHp, bh, 4608, 1, nullptr, 0,    A3);
    gemm_mma<<<dim3(8, 16),  256, GEMM_SMEM>>>(A3, B3p, b3, 4608, 1, nullptr, 0,    A4);
    gemm_mma<<<dim3(4, 16),  256, GEMM_SMEM>>>(A4, B4p, b4, 3072, 1, feature, 512,  A5);
    gemm_mma<<<dim3(16, 16), 256, GEMM_SMEM>>>(A5, B6,  nullptr, 1536, 0, Ms, 2048, nullptr);

    cudaMemsetAsync(oT, 0, (size_t)NB * DB * sizeof(float), 0);
    pairwise_sym<<<dim3(10, DB), 128>>>(Ms, oT);
    final_kernel<<<NB / 8, 256>>>(feature, oT, Wo, bo, logits);
}

// round 15
// speedup vs baseline: 1.7131x; 1.0668x over previous
#include <cuda_runtime.h>
#include <cuda_bf16.h>
#include <cstdint>

typedef unsigned short u16;
typedef unsigned long long u64;

#define H 512
#define DB 128
#define DC 16
#define NB 2048

// ---------------- scratch panels (bf16 x3 split, K' = 3K concatenation) ----------------
__device__ __align__(16) u16 g_A0[2048 * 1536];
__device__ __align__(16) u16 g_A1[2048 * 3072];
__device__ __align__(16) u16 g_A2[2048 * 4608];
__device__ __align__(16) u16 g_A3[2048 * 4608];
__device__ __align__(16) u16 g_A4[2048 * 3072];
__device__ __align__(16) u16 g_A5[2048 * 1536];
__device__ __align__(16) u16 g_B1[1024 * 1536];
__device__ __align__(16) u16 g_B2[1536 * 3072];
__device__ __align__(16) u16 g_BH[1536 * 4608];
__device__ __align__(16) u16 g_B3[1024 * 4608];
__device__ __align__(16) u16 g_B4[512  * 3072];
__device__ __align__(16) u16 g_B6[2048 * 1536];
__device__ __align__(16) float g_Ms[NB * DB * DC];
__device__ __align__(16) float g_outT[NB * DB];

// ---------------- helpers ----------------
__device__ __forceinline__ uint32_t smem_u32(const void* p) {
    uint32_t a;
    asm("{ .reg .u64 t; cvta.to.shared.u64 t, %1; cvt.u32.u64 %0, t; }" : "=r"(a) : "l"(p));
    return a;
}
__device__ __forceinline__ void cp16(uint32_t s, const void* g) {
    asm volatile("cp.async.cg.shared.global [%0], [%1], 16;" :: "r"(s), "l"(g) : "memory");
}
__device__ __forceinline__ void cp_commit() { asm volatile("cp.async.commit_group;" ::: "memory"); }
__device__ __forceinline__ void cp_wait1()  { asm volatile("cp.async.wait_group 1;" ::: "memory"); }
__device__ __forceinline__ void cp_wait0()  { asm volatile("cp.async.wait_group 0;" ::: "memory"); }

__device__ __forceinline__ void ldmx4(uint32_t& r0, uint32_t& r1, uint32_t& r2, uint32_t& r3,
                                      uint32_t addr)
{
    asm volatile("ldmatrix.sync.aligned.m8n8.x4.shared.b16 {%0,%1,%2,%3}, [%4];"
        : "=r"(r0), "=r"(r1), "=r"(r2), "=r"(r3) : "r"(addr));
}

__device__ __forceinline__ void mma_bf16(float* d,
    uint32_t a0, uint32_t a1, uint32_t a2, uint32_t a3, uint32_t b0, uint32_t b1)
{
    asm volatile("mma.sync.aligned.m16n8k16.row.col.f32.bf16.bf16.f32 "
        "{%0,%1,%2,%3}, {%4,%5,%6,%7}, {%8,%9}, {%0,%1,%2,%3};"
        : "+f"(d[0]), "+f"(d[1]), "+f"(d[2]), "+f"(d[3])
        : "r"(a0), "r"(a1), "r"(a2), "r"(a3), "r"(b0), "r"(b1));
}

__device__ __forceinline__ void split8(const float* x, uint4& hv, uint4& lv) {
    unsigned hs[8], ls[8];
#pragma unroll
    for (int i = 0; i < 8; i++) {
        __nv_bfloat16 h = __float2bfloat16(x[i]);
        float hf = __bfloat162float(h);
        __nv_bfloat16 l = __float2bfloat16(x[i] - hf);
        hs[i] = (unsigned)__bfloat16_as_ushort(h);
        ls[i] = (unsigned)__bfloat16_as_ushort(l);
    }
    hv.x = hs[0] | (hs[1] << 16); hv.y = hs[2] | (hs[3] << 16);
    hv.z = hs[4] | (hs[5] << 16); hv.w = hs[6] | (hs[7] << 16);
    lv.x = ls[0] | (ls[1] << 16); lv.y = ls[2] | (ls[3] << 16);
    lv.z = ls[4] | (ls[5] << 16); lv.w = ls[6] | (ls[7] << 16);
}

// ---------------- convert A: fp32 [NB,K] -> A' bf16 [NB, 3K] = [Ah|Al|Ah] ----------------
__global__ __launch_bounds__(256) void convert_A(
    const float* __restrict__ A, u16* __restrict__ P, int K)
{
    int CPR = K >> 3;
    int id = blockIdx.x * 256 + threadIdx.x;
    if (id >= NB * CPR) return;
    int r = id / CPR, c8 = id - r * CPR;
    float x[8];
    *(float4*)&x[0] = *(const float4*)&A[(size_t)r * K + c8 * 8];
    *(float4*)&x[4] = *(const float4*)&A[(size_t)r * K + c8 * 8 + 4];
    uint4 hv, lv;
    split8(x, hv, lv);
    int K3 = 3 * K;
    size_t base = (size_t)r * K3 + c8 * 8;
    *(uint4*)&P[base]         = hv;
    *(uint4*)&P[base + K]     = lv;
    *(uint4*)&P[base + 2 * K] = hv;
}

// ---------------- convert B: W fp32 [K,N] -> B' bf16 [N, 3K] = [Bh|Bh|Bl] ----------------
__global__ __launch_bounds__(256) void convert_B(
    const float* __restrict__ W, u16* __restrict__ P, int K, int N)
{
    __shared__ float ts[64][68];
    int n0 = blockIdx.x * 64, k0 = blockIdx.y * 64;
#pragma unroll
    for (int t = 0; t < 4; t++) {
        int i = threadIdx.x + t * 256;
        int row = i >> 4, q = i & 15;
        *(float4*)&ts[row][q * 4] = *(const float4*)&W[(size_t)(k0 + row) * N + n0 + q * 4];
    }
    __syncthreads();
    int K3 = 3 * K;
#pragma unroll
    for (int t = 0; t < 2; t++) {
        int s = threadIdx.x + t * 256;
        int n = s >> 3, c8 = s & 7;
        float x[8];
#pragma unroll
        for (int i = 0; i < 8; i++) x[i] = ts[c8 * 8 + i][n];
        uint4 hv, lv;
        split8(x, hv, lv);
        size_t base = (size_t)(n0 + n) * K3 + k0 + c8 * 8;
        *(uint4*)&P[base]         = hv;
        *(uint4*)&P[base + K]     = hv;
        *(uint4*)&P[base + 2 * K] = lv;
    }
}

// ---------------- bf16 mma.sync GEMM: CTA 128x64, warp 32x32, BK=32 ----------------
// 3-stage cp.async ring. Stage layout: A 128x40 u16 (5120), B 64x40 u16 (2560) = 7680 u16.
// bias (64 floats) after 3 stages. Total smem = 3*7680*2 + 256 = 46336 B.
// 8 warps as 4(m) x 2(n); warp tile 32x32 -> acc[2][4][4] = 32 regs.
// Target 3 CTAs/SM: occ 37.5% (vs 12.4% at R12).
#define PADK 40
#define STG_ELEMS 7680
#define GEMM_SMEM 46336

__global__ __launch_bounds__(256, 3) void gemm_mma(
    const u16* __restrict__ A, const u16* __restrict__ B,
    const float* __restrict__ bias, int K3, int relu,
    float* __restrict__ outF, int ldF, u16* __restrict__ outP)
{
    extern __shared__ u16 dsm[];
    float* bias_s = (float*)(dsm + 3 * STG_ELEMS);

    const int tid = threadIdx.x;
    const int m0 = blockIdx.y * 128, n0 = blockIdx.x * 64;
    const int Nfull = gridDim.x * 64;
    const int lane = tid & 31, wid = tid >> 5;
    const int g = lane >> 2, tig = lane & 3;
    const int wm = (wid & 3) * 32, wn = (wid >> 2) * 32;
    const int lrow = ((lane >> 3) & 1) * 8 + (lane & 7);
    const int lcolm = (lane >> 4) * 8;

    if (tid < 64) bias_s[tid] = bias ? bias[n0 + tid] : 0.0f;

    const u16* Ag = A + (size_t)m0 * K3;
    const u16* Bg = B + (size_t)n0 * K3;

    float acc[2][4][4];
#pragma unroll
    for (int mf = 0; mf < 2; mf++)
#pragma unroll
        for (int nf = 0; nf < 4; nf++)
#pragma unroll
            for (int q = 0; q < 4; q++) acc[mf][nf][q] = 0.0f;

    const int nchunk = K3 >> 5;
    const int lr = tid >> 2;            // 0..63
    const int lc = (tid & 3) * 8;

    // prefetch chunks 0,1 into stages 0,1
#pragma unroll
    for (int pf = 0; pf < 2; pf++) {
        u16* As = dsm + pf * STG_ELEMS;
        u16* Bs = As + 5120;
        int k0 = pf << 5;
#pragma unroll
        for (int p = 0; p < 2; p++) {
            int r = lr + p * 64;
            cp16(smem_u32(&As[r * PADK + lc]), Ag + (size_t)r * K3 + k0 + lc);
        }
        cp16(smem_u32(&Bs[lr * PADK + lc]), Bg + (size_t)lr * K3 + k0 + lc);
        cp_commit();
    }

    int sc = 0, si = 2;
    for (int kc = 0; kc < nchunk; kc++) {
        if (kc + 1 < nchunk) cp_wait1(); else cp_wait0();
        __syncthreads();

        if (kc + 2 < nchunk) {
            u16* As = dsm + si * STG_ELEMS;
            u16* Bs = As + 5120;
            int k0 = (kc + 2) << 5;
#pragma unroll
            for (int p = 0; p < 2; p++) {
                int r = lr + p * 64;
                cp16(smem_u32(&As[r * PADK + lc]), Ag + (size_t)r * K3 + k0 + lc);
            }
            cp16(smem_u32(&Bs[lr * PADK + lc]), Bg + (size_t)lr * K3 + k0 + lc);
            cp_commit();
        }

        const u16* Asb = dsm + sc * STG_ELEMS;
        const u16* Bsb = Asb + 5120;
#pragma unroll
        for (int ks = 0; ks < 2; ks++) {
            const int kk = (ks << 4) + lcolm;
            uint32_t bfr[4][2];
#pragma unroll
            for (int np = 0; np < 2; np++) {
                uint32_t r0, r1, r2, r3;
                ldmx4(r0, r1, r2, r3,
                      smem_u32(&Bsb[(wn + np * 16 + lrow) * PADK + kk]));
                bfr[np * 2][0] = r0; bfr[np * 2 + 1][0] = r1;
                bfr[np * 2][1] = r2; bfr[np * 2 + 1][1] = r3;
            }
#pragma unroll
            for (int mf = 0; mf < 2; mf++) {
                uint32_t a0, a1, a2, a3;
                ldmx4(a0, a1, a2, a3,
                      smem_u32(&Asb[(wm + mf * 16 + lrow) * PADK + kk]));
#pragma unroll
                for (int nf = 0; nf < 4; nf++)
                    mma_bf16(acc[mf][nf], a0, a1, a2, a3, bfr[nf][0], bfr[nf][1]);
            }
        }

        sc = (sc == 2) ? 0 : sc + 1;
        si = (si == 2) ? 0 : si + 1;
    }

    // epilogue: bias + relu; optional fp32 out; optional next-layer A' panel [M, 3N] = [Ah|Al|Ah]
    const int K3n = 3 * Nfull;
#pragma unroll
    for (int mf = 0; mf < 2; mf++) {
#pragma unroll
        for (int hrow = 0; hrow < 2; hrow++) {
            int row = m0 + wm + mf * 16 + g + hrow * 8;
#pragma unroll
            for (int nf = 0; nf < 4; nf++) {
                int cl = wn + nf * 8 + tig * 2;
                float v0 = acc[mf][nf][hrow * 2 + 0] + bias_s[cl];
                float v1 = acc[mf][nf][hrow * 2 + 1] + bias_s[cl + 1];
                if (relu) { v0 = fmaxf(v0, 0.0f); v1 = fmaxf(v1, 0.0f); }
                int col = n0 + cl;
                if (outF)
                    *(float2*)&outF[(size_t)row * ldF + col] = make_float2(v0, v1);
                if (outP) {
                    __nv_bfloat16 h0 = __float2bfloat16(v0), h1 = __float2bfloat16(v1);
                    float l0 = v0 - __bfloat162float(h0);
                    float l1 = v1 - __bfloat162float(h1);
                    __nv_bfloat16 g0 = __float2bfloat16(l0), g1 = __float2bfloat16(l1);
                    uint32_t hp = (uint32_t)__bfloat16_as_ushort(h0) |
                                  ((uint32_t)__bfloat16_as_ushort(h1) << 16);
                    uint32_t lp = (uint32_t)__bfloat16_as_ushort(g0) |
                                  ((uint32_t)__bfloat16_as_ushort(g1) << 16);
                    size_t base = (size_t)row * K3n + col;
                    *(uint32_t*)&outP[base]             = hp;
                    *(uint32_t*)&outP[base + Nfull]     = lp;
                    *(uint32_t*)&outP[base + 2 * Nfull] = hp;
                }
            }
        }
    }
}

// ---------------- packed f32x2 helpers ----------------
__device__ __forceinline__ u64 fma2_u64(u64 a, u64 b, u64 c)
{
    u64 r;
    asm("fma.rn.f32x2 %0, %1, %2, %3;" : "=l"(r) : "l"(a), "l"(b), "l"(c));
    return r;
}
__device__ __forceinline__ u64 add2_u64(u64 a, u64 b)
{
    u64 r;
    asm("add.rn.f32x2 %0, %1, %2;" : "=l"(r) : "l"(a), "l"(b));
    return r;
}

// ---------------- minibatch discrimination (symmetric, register-blocked R=4) ----------------
__global__ __launch_bounds__(128) void pairwise_sym(
    const float* __restrict__ Ms, float* __restrict__ outT)
{
    const int pair = blockIdx.x;   // 0..9
    const int b = blockIdx.y;
    int ti, tj;
    if (pair < 4)      { ti = 0; tj = pair; }
    else if (pair < 7) { ti = 1; tj = pair - 3; }
    else if (pair < 9) { ti = 2; tj = pair - 5; }
    else               { ti = 3; tj = 3; }
    const bool diag = (ti == tj);

    const int t = threadIdx.x, lane = t & 31, wid = t >> 5;
    const u64 NEG1x2 = 0xBF800000BF800000ull;
    const u64 ABSM   = 0x7FFFFFFF7FFFFFFFull;

    __shared__ u64  sj2[4][512][2];
    __shared__ float sacc[4][512];

#pragma unroll
    for (int rb = 0; rb < 4; rb++) {
        int j = rb * 128 + t;
        const float4* src = (const float4*)&Ms[(size_t)(tj * 512 + j) * 2048 + b * 16];
#pragma unroll
        for (int q = 0; q < 4; q++) {
            float4 v = src[q];
            sj2[q][j][0] = (u64)__float_as_uint(v.x) | ((u64)__float_as_uint(v.y) << 32);
            sj2[q][j][1] = (u64)__float_as_uint(v.z) | ((u64)__float_as_uint(v.w) << 32);
        }
    }
#pragma unroll
    for (int k = t; k < 4 * 512; k += 128) ((float*)sacc)[k] = 0.0f;

    u64 mi[4][8];
#pragma unroll
    for (int r = 0; r < 4; r++) {
        const float4* src = (const float4*)&Ms[(size_t)(ti * 512 + r * 128 + t) * 2048 + b * 16];
#pragma unroll
        for (int q = 0; q < 4; q++) {
            float4 v = src[q];
            mi[r][q * 2 + 0] = (u64)__float_as_uint(v.x) | ((u64)__float_as_uint(v.y) << 32);
            mi[r][q * 2 + 1] = (u64)__float_as_uint(v.z) | ((u64)__float_as_uint(v.w) << 32);
        }
    }
    float acc[4] = {0.0f, 0.0f, 0.0f, 0.0f};
    __syncthreads();

    for (int s = 0; s < 512; s++) {
        int j = (lane + s) & 511;
        u64 mj[8];
#pragma unroll
        for (int q = 0; q < 4; q++) {
            ulonglong2 v = *(const ulonglong2*)&sj2[q][j][0];
            mj[q * 2 + 0] = v.x;
            mj[q * 2 + 1] = v.y;
        }
        float esum = 0.0f;
#pragma unroll
        for (int r = 0; r < 4; r++) {
            u64 a2 = fma2_u64(mj[0], NEG1x2, mi[r][0]) & ABSM;
#pragma unroll
            for (int p = 1; p < 8; p++) {
                u64 d = fma2_u64(mj[p], NEG1x2, mi[r][p]) & ABSM;
                a2 = add2_u64(a2, d);
            }
            float lo = __uint_as_float((unsigned)(a2 & 0xffffffffu));
            float hi = __uint_as_float((unsigned)(a2 >> 32));
            float e = __expf(-(lo + hi));
            acc[r] += e;
            esum += e;
        }
        if (!diag) sacc[wid][j] += esum;
    }
    __syncthreads();

#pragma unroll
    for (int r = 0; r < 4; r++)
        atomicAdd(&outT[(size_t)(ti * 512 + r * 128 + t) * DB + b], acc[r]);
    if (!diag) {
#pragma unroll
        for (int j = t; j < 512; j += 128) {
            float v = sacc[0][j] + sacc[1][j] + sacc[2][j] + sacc[3][j];
            atomicAdd(&outT[(size_t)(tj * 512 + j) * DB + b], v);
        }
    }
}

// ---------------- final logits ----------------
__global__ __launch_bounds__(256) void final_kernel(
    const float* __restrict__ feature, const float* __restrict__ outT,
    const float* __restrict__ Wo, const float* __restrict__ bo,
    float* __restrict__ out)
{
    const int warp = threadIdx.x >> 5;
    const int lane = threadIdx.x & 31;
    const int row = blockIdx.x * 8 + warp;
    if (row >= NB) return;

    float s = 0.0f;
#pragma unroll
    for (int h = lane; h < H; h += 32)
        s = fmaf(feature[(size_t)row * H + h], Wo[h], s);
#pragma unroll
    for (int c = lane; c < DB; c += 32)
        s = fmaf(outT[(size_t)row * DB + c], Wo[H + c], s);
#pragma unroll
    for (int o = 16; o > 0; o >>= 1)
        s += __shfl_xor_sync(0xffffffffu, s, o);
    if (lane == 0) {
        float v = s + bo[0];
        out[row] = 1.0f / (1.0f + __expf(-v));
    }
}

// ---------------- launch ----------------
extern "C" void kernel_launch(void* const* d_in, const int* in_sizes, int n_in,
                              void* d_out, int out_size)
{
    const float* input = (const float*)d_in[0];
    const float* W1 = (const float*)d_in[1];
    const float* b1 = (const float*)d_in[2];
    const float* W2 = (const float*)d_in[3];
    const float* b2 = (const float*)d_in[4];
    const float* Wh = (const float*)d_in[5];
    const float* bh = (const float*)d_in[6];
    const float* W3 = (const float*)d_in[7];
    const float* b3 = (const float*)d_in[8];
    const float* W4 = (const float*)d_in[9];
    const float* b4 = (const float*)d_in[10];
    const float* Wo = (const float*)d_in[11];
    const float* bo = (const float*)d_in[12];
    const float* T  = (const float*)d_in[13];

    float* out = (float*)d_out;
    float* feature = out;
    float* logits = out + (size_t)NB * H;

    u16 *A0, *A1, *A2, *A3, *A4, *A5, *B1, *B2, *BHp, *B3p, *B4p, *B6;
    float *Ms, *oT;
    cudaGetSymbolAddress((void**)&A0, g_A0);
    cudaGetSymbolAddress((void**)&A1, g_A1);
    cudaGetSymbolAddress((void**)&A2, g_A2);
    cudaGetSymbolAddress((void**)&A3, g_A3);
    cudaGetSymbolAddress((void**)&A4, g_A4);
    cudaGetSymbolAddress((void**)&A5, g_A5);
    cudaGetSymbolAddress((void**)&B1, g_B1);
    cudaGetSymbolAddress((void**)&B2, g_B2);
    cudaGetSymbolAddress((void**)&BHp, g_BH);
    cudaGetSymbolAddress((void**)&B3p, g_B3);
    cudaGetSymbolAddress((void**)&B4p, g_B4);
    cudaGetSymbolAddress((void**)&B6, g_B6);
    cudaGetSymbolAddress((void**)&Ms, g_Ms);
    cudaGetSymbolAddress((void**)&oT, g_outT);

    cudaFuncSetAttribute(gemm_mma, cudaFuncAttributeMaxDynamicSharedMemorySize, GEMM_SMEM);

    // Profiler capture slot = my launch #4 -> gemm L1 there.
    convert_A<<<(NB * (512 / 8) + 255) / 256, 256>>>(input, A0, 512);                // #1
    convert_B<<<dim3(1024 / 64, 512 / 64),  256>>>(W1, B1, 512, 1024);               // #2
    convert_B<<<dim3(1536 / 64, 1024 / 64), 256>>>(W2, B2, 1024, 1536);              // #3
    gemm_mma<<<dim3(16, 16), 256, GEMM_SMEM>>>(A0, B1, b1, 1536, 1, nullptr, 0, A1); // #4 <- profiled
    convert_B<<<dim3(1536 / 64, 1536 / 64), 256>>>(Wh, BHp, 1536, 1536);             // #5
    convert_B<<<dim3(1024 / 64, 1536 / 64), 256>>>(W3, B3p, 1536, 1024);             // #6
    convert_B<<<dim3(512 / 64, 1024 / 64),  256>>>(W4, B4p, 1024, 512);              // #7
    convert_B<<<dim3(2048 / 64, 512 / 64),  256>>>(T, B6, 512, 2048);                // #8

    gemm_mma<<<dim3(24, 16), 256, GEMM_SMEM>>>(A1, B2,  b2, 3072, 1, nullptr, 0,    A2);
    gemm_mma<<<dim3(24, 16), 256, GEMM_SMEM>>>(A2, BHp, bh, 4608, 1, nullptr, 0,    A3);
    gemm_mma<<<dim3(16, 16), 256, GEMM_SMEM>>>(A3, B3p, b3, 4608, 1, nullptr, 0,    A4);
    gemm_mma<<<dim3(8, 16),  256, GEMM_SMEM>>>(A4, B4p, b4, 3072, 1, feature, 512,  A5);
    gemm_mma<<<dim3(32, 16), 256, GEMM_SMEM>>>(A5, B6,  nullptr, 1536, 0, Ms, 2048, nullptr);

    cudaMemsetAsync(oT, 0, (size_t)NB * DB * sizeof(float), 0);
    pairwise_sym<<<dim3(10, DB), 128>>>(Ms, oT);
    final_kernel<<<NB / 8, 256>>>(feature, oT, Wo, bo, logits);
}